// round 13
// baseline (speedup 1.0000x reference)
#include <cuda_runtime.h>
#include <cuda_bf16.h>
#include <cuda_fp16.h>
#include <cstdint>
#include <math.h>

#define BATCH 2
#define LSEQ 1024
#define DIMM 1024
#define DSTATE 16
#define DINNER 2048
#define DTRANK 64
#define NROWS (BATCH * LSEQ)   // 2048
#define DBLP_N 128             // padded 96 -> 128
#define KSPLIT 16

// ---------------- scratch ----------------
__device__ __align__(128) __nv_bfloat16 g_xh[NROWS * DIMM];
__device__ __align__(128) __nv_bfloat16 g_xl[NROWS * DIMM];
__device__ __align__(128) __half        g_x16[NROWS * DIMM];
__device__ __align__(128) __nv_bfloat16 g_WinTh[DINNER * DIMM];
__device__ __align__(128) __nv_bfloat16 g_WinTl[DINNER * DIMM];
__device__ __align__(128) __half        g_WzT16[DINNER * DIMM];
__device__ __align__(128) float         g_u[NROWS * DINNER];
__device__ __align__(128) float         g_z[NROWS * DINNER];
__device__ __align__(128) float         g_uc[NROWS * DINNER];
__device__ __align__(128) __nv_bfloat16 g_uch[NROWS * DINNER];
__device__ __align__(128) __nv_bfloat16 g_ucl[NROWS * DINNER];
__device__ __align__(128) __nv_bfloat16 g_WxTh[DBLP_N * DINNER];
__device__ __align__(128) __nv_bfloat16 g_WxTl[DBLP_N * DINNER];
__device__ __align__(128) float         g_dblpp[KSPLIT * NROWS * DBLP_N];
__device__ __align__(128) float         g_dblp[NROWS * DBLP_N];
__device__ __align__(128) __nv_bfloat16 g_dtAh[NROWS * DTRANK];
__device__ __align__(128) __nv_bfloat16 g_dtAl[NROWS * DTRANK];
__device__ __align__(128) __nv_bfloat16 g_WdtTh[DINNER * DTRANK];
__device__ __align__(128) __nv_bfloat16 g_WdtTl[DINNER * DTRANK];
__device__ __align__(128) float         g_dt[NROWS * DINNER];
__device__ __align__(128) __half        g_yg16[NROWS * DINNER];
__device__ __align__(128) __half        g_WoutT16[DIMM * DINNER];

// ---------------- helpers ----------------
__device__ __forceinline__ uint32_t smem_to_u32(const void* p) {
    uint32_t a;
    asm("{ .reg .u64 t; cvta.to.shared.u64 t, %1; cvt.u32.u64 %0, t; }" : "=r"(a) : "l"(p));
    return a;
}
__device__ __forceinline__ void cp_async16(uint32_t dst, const void* src) {
    asm volatile("cp.async.cg.shared.global [%0], [%1], 16;" :: "r"(dst), "l"(src) : "memory");
}
#define CP_COMMIT() asm volatile("cp.async.commit_group;" ::: "memory")
#define CP_WAIT(n)  asm volatile("cp.async.wait_group %0;" :: "n"(n) : "memory")

__device__ __forceinline__ void ldm_x4(uint32_t addr, uint32_t& r0, uint32_t& r1,
                                       uint32_t& r2, uint32_t& r3) {
    asm volatile("ldmatrix.sync.aligned.m8n8.x4.shared.b16 {%0,%1,%2,%3}, [%4];"
                 : "=r"(r0), "=r"(r1), "=r"(r2), "=r"(r3) : "r"(addr));
}
__device__ __forceinline__ void mma_bf16(float* c, const uint32_t* a, const uint32_t* b) {
    asm volatile(
        "mma.sync.aligned.m16n8k16.row.col.f32.bf16.bf16.f32 "
        "{%0,%1,%2,%3}, {%4,%5,%6,%7}, {%8,%9}, {%0,%1,%2,%3};"
        : "+f"(c[0]), "+f"(c[1]), "+f"(c[2]), "+f"(c[3])
        : "r"(a[0]), "r"(a[1]), "r"(a[2]), "r"(a[3]), "r"(b[0]), "r"(b[1]));
}
__device__ __forceinline__ void mma_fp16(float* c, const uint32_t* a, const uint32_t* b) {
    asm volatile(
        "mma.sync.aligned.m16n8k16.row.col.f32.f16.f16.f32 "
        "{%0,%1,%2,%3}, {%4,%5,%6,%7}, {%8,%9}, {%0,%1,%2,%3};"
        : "+f"(c[0]), "+f"(c[1]), "+f"(c[2]), "+f"(c[3])
        : "r"(a[0]), "r"(a[1]), "r"(a[2]), "r"(a[3]), "r"(b[0]), "r"(b[1]));
}

#define PITCH 80
#define TILE_B (128 * PITCH)
#define G3_STAGE (4 * TILE_B)          // 40960
#define G3_SMEM (4 * G3_STAGE + 128)   // 1 CTA/SM, 4-stage
#define GH_STAGE (2 * TILE_B)          // 20480 (R10 verified config)
#define GH_SMEM (4 * GH_STAGE + 128)   // 82048 -> 2 CTAs/SM

// ============================================================
// bf16x3 HMMA GEMM — 4-stage. SPLIT: deterministic split-K partials.
// ============================================================
template <int EPI, int SPLIT>
__global__ __launch_bounds__(256, 1) void gemm3_k(
    const __nv_bfloat16* __restrict__ Ah, const __nv_bfloat16* __restrict__ Al,
    const __nv_bfloat16* __restrict__ Bh, const __nv_bfloat16* __restrict__ Bl,
    float* __restrict__ C, const float* __restrict__ bias,
    int ld, int kLen, int ldc)
{
    extern __shared__ char smraw[];
    const uint32_t s0 = (smem_to_u32(smraw) + 127) & ~127u;

    const int tid = threadIdx.x;
    const int wid = tid >> 5;
    const int lane = tid & 31;
    const int wr = wid >> 2;
    const int wc = wid & 3;
    const int row0 = blockIdx.y * 128;
    const int col0 = blockIdx.x * 128;
    const int kBase = blockIdx.z * kLen;

    float acc[4][4][4];
#pragma unroll
    for (int i = 0; i < 4; i++)
#pragma unroll
        for (int j = 0; j < 4; j++)
#pragma unroll
            for (int q = 0; q < 4; q++) acc[i][j][q] = 0.f;

    const int NC = kLen >> 5;

    auto load_stage = [&](int stage, int kOff) {
        const uint32_t sbuf = s0 + stage * G3_STAGE;
#pragma unroll
        for (int t = 0; t < 4; t++) {
            const __nv_bfloat16* src = (t == 0) ? Ah : (t == 1) ? Al : (t == 2) ? Bh : Bl;
            const int rb = (t < 2) ? row0 : col0;
            const __nv_bfloat16* base = src + (size_t)rb * ld + kBase + kOff;
#pragma unroll
            for (int i2 = 0; i2 < 2; i2++) {
                int i = tid + i2 * 256;
                int r = i >> 2, c4 = i & 3;
                cp_async16(sbuf + t * TILE_B + r * PITCH + c4 * 16,
                           base + (size_t)r * ld + c4 * 8);
            }
        }
    };

    load_stage(0, 0); CP_COMMIT();
    load_stage(1, 32); CP_COMMIT();

    const int a_r = ((lane >> 3) & 1) * 8 + (lane & 7);
    const int a_c = (lane >> 4) * 8;
    const int b_r = ((lane >> 4) & 1) * 8 + (lane & 7);
    const int b_c = ((lane >> 3) & 1) * 8;

    for (int c = 0; c < NC; c++) {
        if (c + 2 < NC) load_stage((c + 2) & 3, (c + 2) << 5);
        CP_COMMIT();
        CP_WAIT(2);
        __syncthreads();

        const uint32_t stg = s0 + (c & 3) * G3_STAGE;
#pragma unroll
        for (int s = 0; s < 2; s++) {
            const int k0 = s * 16;
            uint32_t fAh[4][4], fAl[4][4], fBh[4][2], fBl[4][2];
#pragma unroll
            for (int i = 0; i < 4; i++) {
                uint32_t ar = stg + (wr * 64 + i * 16 + a_r) * PITCH + (k0 + a_c) * 2;
                ldm_x4(ar, fAh[i][0], fAh[i][1], fAh[i][2], fAh[i][3]);
                ldm_x4(ar + TILE_B, fAl[i][0], fAl[i][1], fAl[i][2], fAl[i][3]);
            }
#pragma unroll
            for (int j2 = 0; j2 < 2; j2++) {
                uint32_t br = stg + 2 * TILE_B + (wc * 32 + j2 * 16 + b_r) * PITCH + (k0 + b_c) * 2;
                uint32_t r0, r1, r2, r3;
                ldm_x4(br, r0, r1, r2, r3);
                fBh[j2 * 2][0] = r0; fBh[j2 * 2][1] = r1;
                fBh[j2 * 2 + 1][0] = r2; fBh[j2 * 2 + 1][1] = r3;
                ldm_x4(br + TILE_B, r0, r1, r2, r3);
                fBl[j2 * 2][0] = r0; fBl[j2 * 2][1] = r1;
                fBl[j2 * 2 + 1][0] = r2; fBl[j2 * 2 + 1][1] = r3;
            }
#pragma unroll
            for (int i = 0; i < 4; i++)
#pragma unroll
                for (int j = 0; j < 4; j++) mma_bf16(acc[i][j], fAh[i], fBh[j]);
#pragma unroll
            for (int i = 0; i < 4; i++)
#pragma unroll
                for (int j = 0; j < 4; j++) mma_bf16(acc[i][j], fAh[i], fBl[j]);
#pragma unroll
            for (int i = 0; i < 4; i++)
#pragma unroll
                for (int j = 0; j < 4; j++) mma_bf16(acc[i][j], fAl[i], fBh[j]);
        }
        __syncthreads();
    }

    float* Cz = SPLIT ? (C + (size_t)blockIdx.z * NROWS * ldc) : C;
    const int er = lane >> 2;
    const int ec = (lane & 3) * 2;
#pragma unroll
    for (int i = 0; i < 4; i++) {
#pragma unroll
        for (int j = 0; j < 4; j++) {
            int grow = row0 + wr * 64 + i * 16 + er;
            int gcol = col0 + wc * 32 + j * 8 + ec;
            float v0 = acc[i][j][0], v1 = acc[i][j][1];
            float v2 = acc[i][j][2], v3 = acc[i][j][3];
            if (EPI == 1) {
                float b0 = bias[gcol], b1 = bias[gcol + 1];
                v0 += b0; v1 += b1; v2 += b0; v3 += b1;
                v0 = fmaxf(v0, 0.f) + log1pf(expf(-fabsf(v0)));
                v1 = fmaxf(v1, 0.f) + log1pf(expf(-fabsf(v1)));
                v2 = fmaxf(v2, 0.f) + log1pf(expf(-fabsf(v2)));
                v3 = fmaxf(v3, 0.f) + log1pf(expf(-fabsf(v3)));
            }
            *(float2*)&Cz[(size_t)grow * ldc + gcol] = make_float2(v0, v1);
            *(float2*)&Cz[(size_t)(grow + 8) * ldc + gcol] = make_float2(v2, v3);
        }
    }
}

// ============================================================
// Deterministic split-K reduce + dtA split (merged)
// ============================================================
__global__ __launch_bounds__(256) void reduce_dta_k(
    const float* __restrict__ part, float* __restrict__ dblp,
    __nv_bfloat16* __restrict__ dtAh, __nv_bfloat16* __restrict__ dtAl)
{
    int idx = blockIdx.x * blockDim.x + threadIdx.x;   // float4 index
    if (idx >= NROWS * DBLP_N / 4) return;
    float4 s = ((const float4*)part)[idx];
#pragma unroll
    for (int k = 1; k < KSPLIT; k++) {
        float4 v = ((const float4*)(part + (size_t)k * NROWS * DBLP_N))[idx];
        s.x += v.x; s.y += v.y; s.z += v.z; s.w += v.w;
    }
    ((float4*)dblp)[idx] = s;

    int c4 = idx & 31;            // float4 column within 128-wide row
    if (c4 < 16) {                // columns 0..63 -> dtA
        int r = idx >> 5;
        int col = c4 * 4;
        float v[4] = {s.x, s.y, s.z, s.w};
        __nv_bfloat16 h[4], l[4];
#pragma unroll
        for (int q = 0; q < 4; q++) {
            h[q] = __float2bfloat16(v[q]);
            l[q] = __float2bfloat16(v[q] - __bfloat162float(h[q]));
        }
        *(uint2*)&dtAh[(size_t)r * DTRANK + col] = *(uint2*)h;
        *(uint2*)&dtAl[(size_t)r * DTRANK + col] = *(uint2*)l;
    }
}

// ============================================================
// fp16 1-term HMMA GEMM — R10 verified: BK=32, 2 tiles/stage,
// 4-stage, 2 CTAs/SM
// ============================================================
__global__ __launch_bounds__(256, 2) void gemmh_k(
    const __half* __restrict__ A, const __half* __restrict__ B,
    float* __restrict__ C, int ld, int kLen, int ldc)
{
    extern __shared__ char smraw[];
    const uint32_t s0 = (smem_to_u32(smraw) + 127) & ~127u;

    const int tid = threadIdx.x;
    const int wid = tid >> 5;
    const int lane = tid & 31;
    const int wr = wid >> 2;
    const int wc = wid & 3;
    const int row0 = blockIdx.y * 128;
    const int col0 = blockIdx.x * 128;

    float acc[4][4][4];
#pragma unroll
    for (int i = 0; i < 4; i++)
#pragma unroll
        for (int j = 0; j < 4; j++)
#pragma unroll
            for (int q = 0; q < 4; q++) acc[i][j][q] = 0.f;

    const int NC = kLen >> 5;

    auto load_stage = [&](int stage, int kOff) {
        const uint32_t sbuf = s0 + stage * GH_STAGE;
#pragma unroll
        for (int t = 0; t < 2; t++) {
            const __half* src = (t == 0) ? A : B;
            const int rb = (t == 0) ? row0 : col0;
            const __half* base = src + (size_t)rb * ld + kOff;
#pragma unroll
            for (int i2 = 0; i2 < 2; i2++) {
                int ii = tid + i2 * 256;
                int r = ii >> 2, c4 = ii & 3;
                cp_async16(sbuf + t * TILE_B + r * PITCH + c4 * 16,
                           base + (size_t)r * ld + c4 * 8);
            }
        }
    };

    load_stage(0, 0); CP_COMMIT();
    load_stage(1, 32); CP_COMMIT();

    const int a_r = ((lane >> 3) & 1) * 8 + (lane & 7);
    const int a_c = (lane >> 4) * 8;
    const int b_r = ((lane >> 4) & 1) * 8 + (lane & 7);
    const int b_c = ((lane >> 3) & 1) * 8;

    for (int c = 0; c < NC; c++) {
        if (c + 2 < NC) load_stage((c + 2) & 3, (c + 2) << 5);
        CP_COMMIT();
        CP_WAIT(2);
        __syncthreads();

        const uint32_t stg = s0 + (c & 3) * GH_STAGE;
#pragma unroll
        for (int s = 0; s < 2; s++) {
            const int k0 = s * 16;
            uint32_t fA[4][4], fB[4][2];
#pragma unroll
            for (int i = 0; i < 4; i++) {
                uint32_t ar = stg + (wr * 64 + i * 16 + a_r) * PITCH + (k0 + a_c) * 2;
                ldm_x4(ar, fA[i][0], fA[i][1], fA[i][2], fA[i][3]);
            }
#pragma unroll
            for (int j2 = 0; j2 < 2; j2++) {
                uint32_t br = stg + TILE_B + (wc * 32 + j2 * 16 + b_r) * PITCH + (k0 + b_c) * 2;
                uint32_t r0, r1, r2, r3;
                ldm_x4(br, r0, r1, r2, r3);
                fB[j2 * 2][0] = r0; fB[j2 * 2][1] = r1;
                fB[j2 * 2 + 1][0] = r2; fB[j2 * 2 + 1][1] = r3;
            }
#pragma unroll
            for (int i = 0; i < 4; i++)
#pragma unroll
                for (int j = 0; j < 4; j++) mma_fp16(acc[i][j], fA[i], fB[j]);
        }
        __syncthreads();
    }

    const int er = lane >> 2;
    const int ec = (lane & 3) * 2;
#pragma unroll
    for (int i = 0; i < 4; i++)
#pragma unroll
        for (int j = 0; j < 4; j++) {
            int grow = row0 + wr * 64 + i * 16 + er;
            int gcol = col0 + wc * 32 + j * 8 + ec;
            *(float2*)&C[(size_t)grow * ldc + gcol] = make_float2(acc[i][j][0], acc[i][j][1]);
            *(float2*)&C[(size_t)(grow + 8) * ldc + gcol] = make_float2(acc[i][j][2], acc[i][j][3]);
        }
}

// ============================================================
// LayerNorm -> bf16 hi/lo + fp16
// ============================================================
__global__ __launch_bounds__(256) void layernorm_k(
    const float* __restrict__ x, const float* __restrict__ g,
    const float* __restrict__ b, __nv_bfloat16* __restrict__ xh,
    __nv_bfloat16* __restrict__ xl, __half* __restrict__ x16)
{
    const int row = blockIdx.x;
    const float* xr = x + (size_t)row * DIMM;
    float v[4];
    float s = 0.f;
#pragma unroll
    for (int i = 0; i < 4; i++) { v[i] = xr[threadIdx.x + i * 256]; s += v[i]; }
    __shared__ float red[32];
    for (int o = 16; o > 0; o >>= 1) s += __shfl_xor_sync(0xffffffffu, s, o);
    int lane = threadIdx.x & 31, wid = threadIdx.x >> 5;
    if (lane == 0) red[wid] = s;
    __syncthreads();
    if (wid == 0) {
        float t = (lane < 8) ? red[lane] : 0.f;
        for (int o = 4; o > 0; o >>= 1) t += __shfl_xor_sync(0xffffffffu, t, o);
        if (lane == 0) red[0] = t;
    }
    __syncthreads();
    const float mu = red[0] * (1.f / DIMM);
    float s2 = 0.f;
#pragma unroll
    for (int i = 0; i < 4; i++) { float d = v[i] - mu; s2 += d * d; }
    for (int o = 16; o > 0; o >>= 1) s2 += __shfl_xor_sync(0xffffffffu, s2, o);
    if (lane == 0) red[wid] = s2;
    __syncthreads();
    if (wid == 0) {
        float t = (lane < 8) ? red[lane] : 0.f;
        for (int o = 4; o > 0; o >>= 1) t += __shfl_xor_sync(0xffffffffu, t, o);
        if (lane == 0) red[0] = t;
    }
    __syncthreads();
    const float rstd = rsqrtf(red[0] * (1.f / DIMM) + 1e-5f);
#pragma unroll
    for (int i = 0; i < 4; i++) {
        int c = threadIdx.x + i * 256;
        float o = (v[i] - mu) * rstd * g[c] + b[c];
        __nv_bfloat16 h = __float2bfloat16(o);
        xh[(size_t)row * DIMM + c] = h;
        xl[(size_t)row * DIMM + c] = __float2bfloat16(o - __bfloat162float(h));
        x16[(size_t)row * DIMM + c] = __float2half(o);
    }
}

// ============================================================
// Transposes
// ============================================================
__global__ __launch_bounds__(256) void transpose_split_k(
    const float* __restrict__ src, __nv_bfloat16* __restrict__ oh,
    __nv_bfloat16* __restrict__ ol, int R, int Cs, int co, int Cr, int Cout)
{
    __shared__ float t[32][33];
    int tx = threadIdx.x, ty = threadIdx.y;
    int c0 = blockIdx.x * 32, r0 = blockIdx.y * 32;
#pragma unroll
    for (int j = 0; j < 32; j += 8) {
        int r = r0 + ty + j, c = c0 + tx;
        t[ty + j][tx] = (r < R && c < Cr) ? src[(size_t)r * Cs + co + c] : 0.f;
    }
    __syncthreads();
#pragma unroll
    for (int j = 0; j < 32; j += 8) {
        int orow = c0 + ty + j, ocol = r0 + tx;
        if (orow < Cout && ocol < R) {
            float v = t[tx][ty + j];
            __nv_bfloat16 h = __float2bfloat16(v);
            oh[(size_t)orow * R + ocol] = h;
            ol[(size_t)orow * R + ocol] = __float2bfloat16(v - __bfloat162float(h));
        }
    }
}

__global__ __launch_bounds__(256) void transpose_h_k(
    const float* __restrict__ src, __half* __restrict__ o16,
    int R, int Cs, int co, int Cr, int Cout)
{
    __shared__ float t[32][33];
    int tx = threadIdx.x, ty = threadIdx.y;
    int c0 = blockIdx.x * 32, r0 = blockIdx.y * 32;
#pragma unroll
    for (int j = 0; j < 32; j += 8) {
        int r = r0 + ty + j, c = c0 + tx;
        t[ty + j][tx] = (r < R && c < Cr) ? src[(size_t)r * Cs + co + c] : 0.f;
    }
    __syncthreads();
#pragma unroll
    for (int j = 0; j < 32; j += 8) {
        int orow = c0 + ty + j, ocol = r0 + tx;
        if (orow < Cout && ocol < R)
            o16[(size_t)orow * R + ocol] = __float2half(t[tx][ty + j]);
    }
}

// ============================================================
// conv + SiLU
// ============================================================
__global__ __launch_bounds__(256) void conv_silu_k(
    const float* __restrict__ u, const float* __restrict__ conv_w,
    const float* __restrict__ conv_b, float* __restrict__ uc,
    __nv_bfloat16* __restrict__ uch, __nv_bfloat16* __restrict__ ucl)
{
    int idx = blockIdx.x * blockDim.x + threadIdx.x;
    if (idx >= BATCH * LSEQ * DINNER) return;
    int e = idx & (DINNER - 1);
    int bt = idx >> 11;
    int t = bt & (LSEQ - 1);
    int b = bt >> 10;
    float acc = conv_b[e];
    float w0 = conv_w[e * 4 + 0], w1 = conv_w[e * 4 + 1];
    float w2 = conv_w[e * 4 + 2], w3 = conv_w[e * 4 + 3];
    const float* ub = u + (size_t)b * LSEQ * DINNER + e;
    if (t >= 3) acc = fmaf(w0, ub[(size_t)(t - 3) * DINNER], acc);
    if (t >= 2) acc = fmaf(w1, ub[(size_t)(t - 2) * DINNER], acc);
    if (t >= 1) acc = fmaf(w2, ub[(size_t)(t - 1) * DINNER], acc);
    acc = fmaf(w3, ub[(size_t)t * DINNER], acc);
    acc = acc / (1.f + expf(-acc));
    uc[idx] = acc;
    __nv_bfloat16 h = __float2bfloat16(acc);
    uch[idx] = h;
    ucl[idx] = __float2bfloat16(acc - __bfloat162float(h));
}

// ============================================================
// Selective scan + skip + gate — block-staged, TCHUNK=64
// ============================================================
#define TCHUNK 64
#define SC_OFF_UC 4096
#define SC_OFF_Z  8192
#define SC_OFF_BC 12288
#define SC_STAGE 20480
#define SC_NCH (LSEQ / TCHUNK)

__global__ __launch_bounds__(256) void scan_gate_k(
    const float* __restrict__ dt, const float* __restrict__ uc,
    const float* __restrict__ dblp, const float* __restrict__ z,
    const float* __restrict__ A_log, const float* __restrict__ D_skip,
    __half* __restrict__ yg16)
{
    __shared__ __align__(16) char sm[2 * SC_STAGE + TCHUNK * 16 * 2];
    const uint32_t sb = smem_to_u32(sm);
    __half* sy = (__half*)(sm + 2 * SC_STAGE);

    const int tid = threadIdx.x;
    const int w = tid >> 5;
    const int lane = tid & 31;
    const int el = 2 * w + (lane >> 4);
    const int n = lane & 15;
    const int e0 = blockIdx.x * 16;
    const int b = blockIdx.y;
    const int e = e0 + el;
    const size_t bt0 = (size_t)b * LSEQ;

    const float Aen = -expf(A_log[e * DSTATE + n]);
    const float dsk = D_skip[e];
    float h = 0.f;

    auto load_stage = [&](int st, int t0) {
        const uint32_t s = sb + st * SC_STAGE;
#pragma unroll
        for (int i2 = 0; i2 < 5; i2++) {
            int i = tid + i2 * 256;
            if (i < 256) {
                int t = i >> 2, p = i & 3;
                cp_async16(s + t * 64 + p * 16, dt + (bt0 + t0 + t) * DINNER + e0 + p * 4);
            } else if (i < 512) {
                int j = i - 256; int t = j >> 2, p = j & 3;
                cp_async16(s + SC_OFF_UC + t * 64 + p * 16, uc + (bt0 + t0 + t) * DINNER + e0 + p * 4);
            } else if (i < 768) {
                int j = i - 512; int t = j >> 2, p = j & 3;
                cp_async16(s + SC_OFF_Z + t * 64 + p * 16, z + (bt0 + t0 + t) * DINNER + e0 + p * 4);
            } else if (i < 1280) {
                int j = i - 768; int t = j >> 3, p = j & 7;
                cp_async16(s + SC_OFF_BC + t * 128 + p * 16, dblp + (bt0 + t0 + t) * DBLP_N + DTRANK + p * 4);
            }
        }
    };

    load_stage(0, 0); CP_COMMIT();

    for (int c = 0; c < SC_NCH; c++) {
        if (c + 1 < SC_NCH) { load_stage((c + 1) & 1, (c + 1) * TCHUNK); CP_COMMIT(); CP_WAIT(1); }
        else CP_WAIT(0);
        __syncthreads();

        const char* s = sm + (c & 1) * SC_STAGE;
        const float* sdt = (const float*)s;
        const float* suc = (const float*)(s + SC_OFF_UC);
        const float* sz  = (const float*)(s + SC_OFF_Z);
        const float* sbc = (const float*)(s + SC_OFF_BC);

#pragma unroll 4
        for (int tt = 0; tt < TCHUNK; tt++) {
            float dtv = sdt[tt * 16 + el];
            float ucv = suc[tt * 16 + el];
            float Bc = sbc[tt * 32 + n];
            float Cc = sbc[tt * 32 + 16 + n];
            float a = expf(dtv * Aen);
            h = fmaf(a, h, dtv * ucv * Bc);
            float p = h * Cc;
            p += __shfl_xor_sync(0xffffffffu, p, 1);
            p += __shfl_xor_sync(0xffffffffu, p, 2);
            p += __shfl_xor_sync(0xffffffffu, p, 4);
            p += __shfl_xor_sync(0xffffffffu, p, 8);
            if (n == 0) {
                float zv = sz[tt * 16 + el];
                float y = fmaf(ucv, dsk, p);
                y = y * (zv / (1.f + expf(-zv)));
                sy[tt * 16 + el] = __float2half(y);
            }
        }
        __syncthreads();
        for (int i = tid; i < TCHUNK * 16; i += 256) {
            int t = i >> 4, el2 = i & 15;
            yg16[(bt0 + c * TCHUNK + t) * DINNER + e0 + el2] = sy[i];
        }
    }
}

// ============================================================
// Launcher
// ============================================================
extern "C" void kernel_launch(void* const* d_in, const int* in_sizes, int n_in,
                              void* d_out, int out_size)
{
    const float* x      = (const float*)d_in[0];
    const float* ln_g   = (const float*)d_in[1];
    const float* ln_b   = (const float*)d_in[2];
    const float* W_in   = (const float*)d_in[3];
    const float* conv_w = (const float*)d_in[4];
    const float* conv_b = (const float*)d_in[5];
    const float* W_x    = (const float*)d_in[6];
    const float* W_dt   = (const float*)d_in[7];
    const float* b_dt   = (const float*)d_in[8];
    const float* A_log  = (const float*)d_in[9];
    const float* D_skip = (const float*)d_in[10];
    const float* W_out  = (const float*)d_in[11];
    float* out = (float*)d_out;

    __nv_bfloat16 *xh, *xl, *WinTh, *WinTl, *uch, *ucl, *WxTh, *WxTl;
    __nv_bfloat16 *dtAh, *dtAl, *WdtTh, *WdtTl;
    __half *x16, *WzT16, *yg16, *WoutT16;
    float *u, *z, *uc, *dblpp, *dblp, *dt;
    cudaGetSymbolAddress((void**)&xh, g_xh);       cudaGetSymbolAddress((void**)&xl, g_xl);
    cudaGetSymbolAddress((void**)&x16, g_x16);
    cudaGetSymbolAddress((void**)&WinTh, g_WinTh); cudaGetSymbolAddress((void**)&WinTl, g_WinTl);
    cudaGetSymbolAddress((void**)&WzT16, g_WzT16);
    cudaGetSymbolAddress((void**)&u, g_u);         cudaGetSymbolAddress((void**)&z, g_z);
    cudaGetSymbolAddress((void**)&uc, g_uc);
    cudaGetSymbolAddress((void**)&uch, g_uch);     cudaGetSymbolAddress((void**)&ucl, g_ucl);
    cudaGetSymbolAddress((void**)&WxTh, g_WxTh);   cudaGetSymbolAddress((void**)&WxTl, g_WxTl);
    cudaGetSymbolAddress((void**)&dblpp, g_dblpp); cudaGetSymbolAddress((void**)&dblp, g_dblp);
    cudaGetSymbolAddress((void**)&dtAh, g_dtAh);   cudaGetSymbolAddress((void**)&dtAl, g_dtAl);
    cudaGetSymbolAddress((void**)&WdtTh, g_WdtTh); cudaGetSymbolAddress((void**)&WdtTl, g_WdtTl);
    cudaGetSymbolAddress((void**)&dt, g_dt);
    cudaGetSymbolAddress((void**)&yg16, g_yg16);   cudaGetSymbolAddress((void**)&WoutT16, g_WoutT16);

    cudaFuncSetAttribute(gemm3_k<0, 0>, cudaFuncAttributeMaxDynamicSharedMemorySize, G3_SMEM);
    cudaFuncSetAttribute(gemm3_k<0, 1>, cudaFuncAttributeMaxDynamicSharedMemorySize, G3_SMEM);
    cudaFuncSetAttribute(gemm3_k<1, 0>, cudaFuncAttributeMaxDynamicSharedMemorySize, G3_SMEM);
    cudaFuncSetAttribute(gemmh_k, cudaFuncAttributeMaxDynamicSharedMemorySize, GH_SMEM);

    static cudaStream_t s1 = nullptr, s2 = nullptr, s3 = nullptr;
    static cudaEvent_t evRoot = nullptr, evLN = nullptr, evTu = nullptr,
                       evPrep = nullptr, evZ = nullptr;
    if (!s1) {
        cudaStreamCreateWithFlags(&s1, cudaStreamNonBlocking);
        cudaStreamCreateWithFlags(&s2, cudaStreamNonBlocking);
        cudaStreamCreateWithFlags(&s3, cudaStreamNonBlocking);
        cudaEventCreateWithFlags(&evRoot, cudaEventDisableTiming);
        cudaEventCreateWithFlags(&evLN, cudaEventDisableTiming);
        cudaEventCreateWithFlags(&evTu, cudaEventDisableTiming);
        cudaEventCreateWithFlags(&evPrep, cudaEventDisableTiming);
        cudaEventCreateWithFlags(&evZ, cudaEventDisableTiming);
    }

    cudaEventRecord(evRoot, 0);
    cudaStreamWaitEvent(s1, evRoot, 0);
    cudaStreamWaitEvent(s2, evRoot, 0);
    cudaStreamWaitEvent(s3, evRoot, 0);

    // [main #1] LayerNorm
    layernorm_k<<<NROWS, 256, 0, 0>>>(x, ln_g, ln_b, xh, xl, x16);
    cudaEventRecord(evLN, 0);

    // [s1 #2] W_in u-half transpose
    transpose_split_k<<<dim3(64, 32), dim3(32, 8), 0, s1>>>(W_in, WinTh, WinTl, DIMM, 2 * DINNER, 0, DINNER, DINNER);
    cudaEventRecord(evTu, s1);

    // [s2 #3] W_in z-half transpose
    transpose_h_k<<<dim3(64, 32), dim3(32, 8), 0, s2>>>(W_in, WzT16, DIMM, 2 * DINNER, DINNER, DINNER, DINNER);

    // [s2 #4] z = xn @ W_in[:, 2048:]  (fp16, R10 config)  <-- ncu target
    cudaStreamWaitEvent(s2, evLN, 0);
    gemmh_k<<<dim3(DINNER / 128, NROWS / 128), 256, GH_SMEM, s2>>>(
        x16, WzT16, z, DIMM, DIMM, DINNER);
    cudaEventRecord(evZ, s2);

    // [main #5] u = xn @ W_in[:, :2048]  (bf16x3)
    cudaStreamWaitEvent(0, evTu, 0);
    gemm3_k<0, 0><<<dim3(DINNER / 128, NROWS / 128), 256, G3_SMEM, 0>>>(
        xh, xl, WinTh, WinTl, u, nullptr, DIMM, DIMM, DINNER);

    // [s3] remaining weight prep
    transpose_split_k<<<dim3(4, 64), dim3(32, 8), 0, s3>>>(W_x, WxTh, WxTl, DINNER, 96, 0, 96, DBLP_N);
    transpose_split_k<<<dim3(64, 2), dim3(32, 8), 0, s3>>>(W_dt, WdtTh, WdtTl, DTRANK, DINNER, 0, DINNER, DINNER);
    transpose_h_k<<<dim3(32, 64), dim3(32, 8), 0, s3>>>(W_out, WoutT16, DINNER, DIMM, 0, DIMM, DIMM);
    cudaEventRecord(evPrep, s3);

    // [main] conv + SiLU
    conv_silu_k<<<(BATCH * LSEQ * DINNER + 255) / 256, 256, 0, 0>>>(u, conv_w, conv_b, uc, uch, ucl);

    // [main] dblp partials = uc @ W_x (bf16x3, deterministic split-K x16)
    cudaStreamWaitEvent(0, evPrep, 0);
    gemm3_k<0, 1><<<dim3(1, NROWS / 128, KSPLIT), 256, G3_SMEM, 0>>>(
        uch, ucl, WxTh, WxTl, dblpp, nullptr, DINNER, DINNER / KSPLIT, DBLP_N);

    // [main] deterministic reduce + dtA split (merged)
    reduce_dta_k<<<(NROWS * DBLP_N / 4 + 255) / 256, 256, 0, 0>>>(dblpp, dblp, dtAh, dtAl);

    // [main] dt = softplus(dtA @ W_dt + b_dt)
    gemm3_k<1, 0><<<dim3(DINNER / 128, NROWS / 128), 256, G3_SMEM, 0>>>(
        dtAh, dtAl, WdtTh, WdtTl, dt, b_dt, DTRANK, DTRANK, DINNER);

    // [main] scan (needs z)
    cudaStreamWaitEvent(0, evZ, 0);
    scan_gate_k<<<dim3(DINNER / 16, BATCH), 256, 0, 0>>>(
        dt, uc, dblp, z, A_log, D_skip, yg16);

    // [main] out = yg @ W_out  (fp16, R10 config)
    gemmh_k<<<dim3(DIMM / 128, NROWS / 128), 256, GH_SMEM, 0>>>(
        yg16, WoutT16, out, DINNER, DINNER, DIMM);
}

// round 14
// speedup vs baseline: 1.3303x; 1.3303x over previous
#include <cuda_runtime.h>
#include <cuda_bf16.h>
#include <cuda_fp16.h>
#include <cstdint>
#include <math.h>

#define BATCH 2
#define LSEQ 1024
#define DIMM 1024
#define DSTATE 16
#define DINNER 2048
#define DTRANK 64
#define NROWS (BATCH * LSEQ)   // 2048
#define DBLP_N 128             // padded 96 -> 128
#define KSPLIT 16

// ---------------- scratch ----------------
__device__ __align__(128) __nv_bfloat16 g_xh[NROWS * DIMM];
__device__ __align__(128) __nv_bfloat16 g_xl[NROWS * DIMM];
__device__ __align__(128) __half        g_x16[NROWS * DIMM];
__device__ __align__(128) __nv_bfloat16 g_WinTh[DINNER * DIMM];
__device__ __align__(128) __nv_bfloat16 g_WinTl[DINNER * DIMM];
__device__ __align__(128) __half        g_WzT16[DINNER * DIMM];
__device__ __align__(128) float         g_u[NROWS * DINNER];
__device__ __align__(128) float         g_z[NROWS * DINNER];
__device__ __align__(128) float         g_uc[NROWS * DINNER];
__device__ __align__(128) __nv_bfloat16 g_uch[NROWS * DINNER];
__device__ __align__(128) __nv_bfloat16 g_ucl[NROWS * DINNER];
__device__ __align__(128) __nv_bfloat16 g_WxTh[DBLP_N * DINNER];
__device__ __align__(128) __nv_bfloat16 g_WxTl[DBLP_N * DINNER];
__device__ __align__(128) float         g_dblpp[KSPLIT * NROWS * DBLP_N];
__device__ __align__(128) float         g_dblp[NROWS * DBLP_N];
__device__ __align__(128) __nv_bfloat16 g_dtAh[NROWS * DTRANK];
__device__ __align__(128) __nv_bfloat16 g_dtAl[NROWS * DTRANK];
__device__ __align__(128) __nv_bfloat16 g_WdtTh[DINNER * DTRANK];
__device__ __align__(128) __nv_bfloat16 g_WdtTl[DINNER * DTRANK];
__device__ __align__(128) float         g_dt[NROWS * DINNER];
__device__ __align__(128) __half        g_yg16[NROWS * DINNER];
__device__ __align__(128) __half        g_WoutT16[DIMM * DINNER];

// ---------------- helpers ----------------
__device__ __forceinline__ uint32_t smem_to_u32(const void* p) {
    uint32_t a;
    asm("{ .reg .u64 t; cvta.to.shared.u64 t, %1; cvt.u32.u64 %0, t; }" : "=r"(a) : "l"(p));
    return a;
}
__device__ __forceinline__ void cp_async16(uint32_t dst, const void* src) {
    asm volatile("cp.async.cg.shared.global [%0], [%1], 16;" :: "r"(dst), "l"(src) : "memory");
}
#define CP_COMMIT() asm volatile("cp.async.commit_group;" ::: "memory")
#define CP_WAIT(n)  asm volatile("cp.async.wait_group %0;" :: "n"(n) : "memory")

__device__ __forceinline__ void ldm_x4(uint32_t addr, uint32_t& r0, uint32_t& r1,
                                       uint32_t& r2, uint32_t& r3) {
    asm volatile("ldmatrix.sync.aligned.m8n8.x4.shared.b16 {%0,%1,%2,%3}, [%4];"
                 : "=r"(r0), "=r"(r1), "=r"(r2), "=r"(r3) : "r"(addr));
}
__device__ __forceinline__ void mma_bf16(float* c, const uint32_t* a, const uint32_t* b) {
    asm volatile(
        "mma.sync.aligned.m16n8k16.row.col.f32.bf16.bf16.f32 "
        "{%0,%1,%2,%3}, {%4,%5,%6,%7}, {%8,%9}, {%0,%1,%2,%3};"
        : "+f"(c[0]), "+f"(c[1]), "+f"(c[2]), "+f"(c[3])
        : "r"(a[0]), "r"(a[1]), "r"(a[2]), "r"(a[3]), "r"(b[0]), "r"(b[1]));
}
__device__ __forceinline__ void mma_fp16(float* c, const uint32_t* a, const uint32_t* b) {
    asm volatile(
        "mma.sync.aligned.m16n8k16.row.col.f32.f16.f16.f32 "
        "{%0,%1,%2,%3}, {%4,%5,%6,%7}, {%8,%9}, {%0,%1,%2,%3};"
        : "+f"(c[0]), "+f"(c[1]), "+f"(c[2]), "+f"(c[3])
        : "r"(a[0]), "r"(a[1]), "r"(a[2]), "r"(a[3]), "r"(b[0]), "r"(b[1]));
}

#define PITCH 80
#define TILE_B (128 * PITCH)
#define G3_STAGE (4 * TILE_B)
#define G3_SMEM (4 * G3_STAGE + 128)
#define GH_STAGE (2 * TILE_B)
#define GH_SMEM (4 * GH_STAGE + 128)

// ============================================================
// bf16x3 HMMA GEMM — 4-stage. SPLIT: deterministic split-K partials.
// ============================================================
template <int EPI, int SPLIT>
__global__ __launch_bounds__(256, 1) void gemm3_k(
    const __nv_bfloat16* __restrict__ Ah, const __nv_bfloat16* __restrict__ Al,
    const __nv_bfloat16* __restrict__ Bh, const __nv_bfloat16* __restrict__ Bl,
    float* __restrict__ C, const float* __restrict__ bias,
    int ld, int kLen, int ldc)
{
    extern __shared__ char smraw[];
    const uint32_t s0 = (smem_to_u32(smraw) + 127) & ~127u;

    const int tid = threadIdx.x;
    const int wid = tid >> 5;
    const int lane = tid & 31;
    const int wr = wid >> 2;
    const int wc = wid & 3;
    const int row0 = blockIdx.y * 128;
    const int col0 = blockIdx.x * 128;
    const int kBase = blockIdx.z * kLen;

    float acc[4][4][4];
#pragma unroll
    for (int i = 0; i < 4; i++)
#pragma unroll
        for (int j = 0; j < 4; j++)
#pragma unroll
            for (int q = 0; q < 4; q++) acc[i][j][q] = 0.f;

    const int NC = kLen >> 5;

    auto load_stage = [&](int stage, int kOff) {
        const uint32_t sbuf = s0 + stage * G3_STAGE;
#pragma unroll
        for (int t = 0; t < 4; t++) {
            const __nv_bfloat16* src = (t == 0) ? Ah : (t == 1) ? Al : (t == 2) ? Bh : Bl;
            const int rb = (t < 2) ? row0 : col0;
            const __nv_bfloat16* base = src + (size_t)rb * ld + kBase + kOff;
#pragma unroll
            for (int i2 = 0; i2 < 2; i2++) {
                int i = tid + i2 * 256;
                int r = i >> 2, c4 = i & 3;
                cp_async16(sbuf + t * TILE_B + r * PITCH + c4 * 16,
                           base + (size_t)r * ld + c4 * 8);
            }
        }
    };

    load_stage(0, 0); CP_COMMIT();
    load_stage(1, 32); CP_COMMIT();

    const int a_r = ((lane >> 3) & 1) * 8 + (lane & 7);
    const int a_c = (lane >> 4) * 8;
    const int b_r = ((lane >> 4) & 1) * 8 + (lane & 7);
    const int b_c = ((lane >> 3) & 1) * 8;

    for (int c = 0; c < NC; c++) {
        if (c + 2 < NC) load_stage((c + 2) & 3, (c + 2) << 5);
        CP_COMMIT();
        CP_WAIT(2);
        __syncthreads();

        const uint32_t stg = s0 + (c & 3) * G3_STAGE;
#pragma unroll
        for (int s = 0; s < 2; s++) {
            const int k0 = s * 16;
            uint32_t fAh[4][4], fAl[4][4], fBh[4][2], fBl[4][2];
#pragma unroll
            for (int i = 0; i < 4; i++) {
                uint32_t ar = stg + (wr * 64 + i * 16 + a_r) * PITCH + (k0 + a_c) * 2;
                ldm_x4(ar, fAh[i][0], fAh[i][1], fAh[i][2], fAh[i][3]);
                ldm_x4(ar + TILE_B, fAl[i][0], fAl[i][1], fAl[i][2], fAl[i][3]);
            }
#pragma unroll
            for (int j2 = 0; j2 < 2; j2++) {
                uint32_t br = stg + 2 * TILE_B + (wc * 32 + j2 * 16 + b_r) * PITCH + (k0 + b_c) * 2;
                uint32_t r0, r1, r2, r3;
                ldm_x4(br, r0, r1, r2, r3);
                fBh[j2 * 2][0] = r0; fBh[j2 * 2][1] = r1;
                fBh[j2 * 2 + 1][0] = r2; fBh[j2 * 2 + 1][1] = r3;
                ldm_x4(br + TILE_B, r0, r1, r2, r3);
                fBl[j2 * 2][0] = r0; fBl[j2 * 2][1] = r1;
                fBl[j2 * 2 + 1][0] = r2; fBl[j2 * 2 + 1][1] = r3;
            }
#pragma unroll
            for (int i = 0; i < 4; i++)
#pragma unroll
                for (int j = 0; j < 4; j++) mma_bf16(acc[i][j], fAh[i], fBh[j]);
#pragma unroll
            for (int i = 0; i < 4; i++)
#pragma unroll
                for (int j = 0; j < 4; j++) mma_bf16(acc[i][j], fAh[i], fBl[j]);
#pragma unroll
            for (int i = 0; i < 4; i++)
#pragma unroll
                for (int j = 0; j < 4; j++) mma_bf16(acc[i][j], fAl[i], fBh[j]);
        }
        __syncthreads();
    }

    float* Cz = SPLIT ? (C + (size_t)blockIdx.z * NROWS * ldc) : C;
    const int er = lane >> 2;
    const int ec = (lane & 3) * 2;
#pragma unroll
    for (int i = 0; i < 4; i++) {
#pragma unroll
        for (int j = 0; j < 4; j++) {
            int grow = row0 + wr * 64 + i * 16 + er;
            int gcol = col0 + wc * 32 + j * 8 + ec;
            float v0 = acc[i][j][0], v1 = acc[i][j][1];
            float v2 = acc[i][j][2], v3 = acc[i][j][3];
            if (EPI == 1) {
                float b0 = bias[gcol], b1 = bias[gcol + 1];
                v0 += b0; v1 += b1; v2 += b0; v3 += b1;
                v0 = fmaxf(v0, 0.f) + log1pf(expf(-fabsf(v0)));
                v1 = fmaxf(v1, 0.f) + log1pf(expf(-fabsf(v1)));
                v2 = fmaxf(v2, 0.f) + log1pf(expf(-fabsf(v2)));
                v3 = fmaxf(v3, 0.f) + log1pf(expf(-fabsf(v3)));
            }
            *(float2*)&Cz[(size_t)grow * ldc + gcol] = make_float2(v0, v1);
            *(float2*)&Cz[(size_t)(grow + 8) * ldc + gcol] = make_float2(v2, v3);
        }
    }
}

// ============================================================
// Deterministic split-K reduce + dtA split (merged)
// ============================================================
__global__ __launch_bounds__(256) void reduce_dta_k(
    const float* __restrict__ part, float* __restrict__ dblp,
    __nv_bfloat16* __restrict__ dtAh, __nv_bfloat16* __restrict__ dtAl)
{
    int idx = blockIdx.x * blockDim.x + threadIdx.x;
    if (idx >= NROWS * DBLP_N / 4) return;
    float4 s = ((const float4*)part)[idx];
#pragma unroll
    for (int k = 1; k < KSPLIT; k++) {
        float4 v = ((const float4*)(part + (size_t)k * NROWS * DBLP_N))[idx];
        s.x += v.x; s.y += v.y; s.z += v.z; s.w += v.w;
    }
    ((float4*)dblp)[idx] = s;

    int c4 = idx & 31;
    if (c4 < 16) {
        int r = idx >> 5;
        int col = c4 * 4;
        float v[4] = {s.x, s.y, s.z, s.w};
        __nv_bfloat16 h[4], l[4];
#pragma unroll
        for (int q = 0; q < 4; q++) {
            h[q] = __float2bfloat16(v[q]);
            l[q] = __float2bfloat16(v[q] - __bfloat162float(h[q]));
        }
        *(uint2*)&dtAh[(size_t)r * DTRANK + col] = *(uint2*)h;
        *(uint2*)&dtAl[(size_t)r * DTRANK + col] = *(uint2*)l;
    }
}

// ============================================================
// fp16 1-term HMMA GEMM — R10 verified config (2 CTAs/SM)
// ============================================================
__global__ __launch_bounds__(256, 2) void gemmh_k(
    const __half* __restrict__ A, const __half* __restrict__ B,
    float* __restrict__ C, int ld, int kLen, int ldc)
{
    extern __shared__ char smraw[];
    const uint32_t s0 = (smem_to_u32(smraw) + 127) & ~127u;

    const int tid = threadIdx.x;
    const int wid = tid >> 5;
    const int lane = tid & 31;
    const int wr = wid >> 2;
    const int wc = wid & 3;
    const int row0 = blockIdx.y * 128;
    const int col0 = blockIdx.x * 128;

    float acc[4][4][4];
#pragma unroll
    for (int i = 0; i < 4; i++)
#pragma unroll
        for (int j = 0; j < 4; j++)
#pragma unroll
            for (int q = 0; q < 4; q++) acc[i][j][q] = 0.f;

    const int NC = kLen >> 5;

    auto load_stage = [&](int stage, int kOff) {
        const uint32_t sbuf = s0 + stage * GH_STAGE;
#pragma unroll
        for (int t = 0; t < 2; t++) {
            const __half* src = (t == 0) ? A : B;
            const int rb = (t == 0) ? row0 : col0;
            const __half* base = src + (size_t)rb * ld + kOff;
#pragma unroll
            for (int i2 = 0; i2 < 2; i2++) {
                int ii = tid + i2 * 256;
                int r = ii >> 2, c4 = ii & 3;
                cp_async16(sbuf + t * TILE_B + r * PITCH + c4 * 16,
                           base + (size_t)r * ld + c4 * 8);
            }
        }
    };

    load_stage(0, 0); CP_COMMIT();
    load_stage(1, 32); CP_COMMIT();

    const int a_r = ((lane >> 3) & 1) * 8 + (lane & 7);
    const int a_c = (lane >> 4) * 8;
    const int b_r = ((lane >> 4) & 1) * 8 + (lane & 7);
    const int b_c = ((lane >> 3) & 1) * 8;

    for (int c = 0; c < NC; c++) {
        if (c + 2 < NC) load_stage((c + 2) & 3, (c + 2) << 5);
        CP_COMMIT();
        CP_WAIT(2);
        __syncthreads();

        const uint32_t stg = s0 + (c & 3) * GH_STAGE;
#pragma unroll
        for (int s = 0; s < 2; s++) {
            const int k0 = s * 16;
            uint32_t fA[4][4], fB[4][2];
#pragma unroll
            for (int i = 0; i < 4; i++) {
                uint32_t ar = stg + (wr * 64 + i * 16 + a_r) * PITCH + (k0 + a_c) * 2;
                ldm_x4(ar, fA[i][0], fA[i][1], fA[i][2], fA[i][3]);
            }
#pragma unroll
            for (int j2 = 0; j2 < 2; j2++) {
                uint32_t br = stg + TILE_B + (wc * 32 + j2 * 16 + b_r) * PITCH + (k0 + b_c) * 2;
                uint32_t r0, r1, r2, r3;
                ldm_x4(br, r0, r1, r2, r3);
                fB[j2 * 2][0] = r0; fB[j2 * 2][1] = r1;
                fB[j2 * 2 + 1][0] = r2; fB[j2 * 2 + 1][1] = r3;
            }
#pragma unroll
            for (int i = 0; i < 4; i++)
#pragma unroll
                for (int j = 0; j < 4; j++) mma_fp16(acc[i][j], fA[i], fB[j]);
        }
        __syncthreads();
    }

    const int er = lane >> 2;
    const int ec = (lane & 3) * 2;
#pragma unroll
    for (int i = 0; i < 4; i++)
#pragma unroll
        for (int j = 0; j < 4; j++) {
            int grow = row0 + wr * 64 + i * 16 + er;
            int gcol = col0 + wc * 32 + j * 8 + ec;
            *(float2*)&C[(size_t)grow * ldc + gcol] = make_float2(acc[i][j][0], acc[i][j][1]);
            *(float2*)&C[(size_t)(grow + 8) * ldc + gcol] = make_float2(acc[i][j][2], acc[i][j][3]);
        }
}

// ============================================================
// LayerNorm -> bf16 hi/lo + fp16
// ============================================================
__global__ __launch_bounds__(256) void layernorm_k(
    const float* __restrict__ x, const float* __restrict__ g,
    const float* __restrict__ b, __nv_bfloat16* __restrict__ xh,
    __nv_bfloat16* __restrict__ xl, __half* __restrict__ x16)
{
    const int row = blockIdx.x;
    const float* xr = x + (size_t)row * DIMM;
    float v[4];
    float s = 0.f;
#pragma unroll
    for (int i = 0; i < 4; i++) { v[i] = xr[threadIdx.x + i * 256]; s += v[i]; }
    __shared__ float red[32];
    for (int o = 16; o > 0; o >>= 1) s += __shfl_xor_sync(0xffffffffu, s, o);
    int lane = threadIdx.x & 31, wid = threadIdx.x >> 5;
    if (lane == 0) red[wid] = s;
    __syncthreads();
    if (wid == 0) {
        float t = (lane < 8) ? red[lane] : 0.f;
        for (int o = 4; o > 0; o >>= 1) t += __shfl_xor_sync(0xffffffffu, t, o);
        if (lane == 0) red[0] = t;
    }
    __syncthreads();
    const float mu = red[0] * (1.f / DIMM);
    float s2 = 0.f;
#pragma unroll
    for (int i = 0; i < 4; i++) { float d = v[i] - mu; s2 += d * d; }
    for (int o = 16; o > 0; o >>= 1) s2 += __shfl_xor_sync(0xffffffffu, s2, o);
    if (lane == 0) red[wid] = s2;
    __syncthreads();
    if (wid == 0) {
        float t = (lane < 8) ? red[lane] : 0.f;
        for (int o = 4; o > 0; o >>= 1) t += __shfl_xor_sync(0xffffffffu, t, o);
        if (lane == 0) red[0] = t;
    }
    __syncthreads();
    const float rstd = rsqrtf(red[0] * (1.f / DIMM) + 1e-5f);
#pragma unroll
    for (int i = 0; i < 4; i++) {
        int c = threadIdx.x + i * 256;
        float o = (v[i] - mu) * rstd * g[c] + b[c];
        __nv_bfloat16 h = __float2bfloat16(o);
        xh[(size_t)row * DIMM + c] = h;
        xl[(size_t)row * DIMM + c] = __float2bfloat16(o - __bfloat162float(h));
        x16[(size_t)row * DIMM + c] = __float2half(o);
    }
}

// ============================================================
// Transposes
// ============================================================
__global__ __launch_bounds__(256) void transpose_split_k(
    const float* __restrict__ src, __nv_bfloat16* __restrict__ oh,
    __nv_bfloat16* __restrict__ ol, int R, int Cs, int co, int Cr, int Cout)
{
    __shared__ float t[32][33];
    int tx = threadIdx.x, ty = threadIdx.y;
    int c0 = blockIdx.x * 32, r0 = blockIdx.y * 32;
#pragma unroll
    for (int j = 0; j < 32; j += 8) {
        int r = r0 + ty + j, c = c0 + tx;
        t[ty + j][tx] = (r < R && c < Cr) ? src[(size_t)r * Cs + co + c] : 0.f;
    }
    __syncthreads();
#pragma unroll
    for (int j = 0; j < 32; j += 8) {
        int orow = c0 + ty + j, ocol = r0 + tx;
        if (orow < Cout && ocol < R) {
            float v = t[tx][ty + j];
            __nv_bfloat16 h = __float2bfloat16(v);
            oh[(size_t)orow * R + ocol] = h;
            ol[(size_t)orow * R + ocol] = __float2bfloat16(v - __bfloat162float(h));
        }
    }
}

__global__ __launch_bounds__(256) void transpose_h_k(
    const float* __restrict__ src, __half* __restrict__ o16,
    int R, int Cs, int co, int Cr, int Cout)
{
    __shared__ float t[32][33];
    int tx = threadIdx.x, ty = threadIdx.y;
    int c0 = blockIdx.x * 32, r0 = blockIdx.y * 32;
#pragma unroll
    for (int j = 0; j < 32; j += 8) {
        int r = r0 + ty + j, c = c0 + tx;
        t[ty + j][tx] = (r < R && c < Cr) ? src[(size_t)r * Cs + co + c] : 0.f;
    }
    __syncthreads();
#pragma unroll
    for (int j = 0; j < 32; j += 8) {
        int orow = c0 + ty + j, ocol = r0 + tx;
        if (orow < Cout && ocol < R)
            o16[(size_t)orow * R + ocol] = __float2half(t[tx][ty + j]);
    }
}

// ============================================================
// conv + SiLU
// ============================================================
__global__ __launch_bounds__(256) void conv_silu_k(
    const float* __restrict__ u, const float* __restrict__ conv_w,
    const float* __restrict__ conv_b, float* __restrict__ uc,
    __nv_bfloat16* __restrict__ uch, __nv_bfloat16* __restrict__ ucl)
{
    int idx = blockIdx.x * blockDim.x + threadIdx.x;
    if (idx >= BATCH * LSEQ * DINNER) return;
    int e = idx & (DINNER - 1);
    int bt = idx >> 11;
    int t = bt & (LSEQ - 1);
    int b = bt >> 10;
    float acc = conv_b[e];
    float w0 = conv_w[e * 4 + 0], w1 = conv_w[e * 4 + 1];
    float w2 = conv_w[e * 4 + 2], w3 = conv_w[e * 4 + 3];
    const float* ub = u + (size_t)b * LSEQ * DINNER + e;
    if (t >= 3) acc = fmaf(w0, ub[(size_t)(t - 3) * DINNER], acc);
    if (t >= 2) acc = fmaf(w1, ub[(size_t)(t - 2) * DINNER], acc);
    if (t >= 1) acc = fmaf(w2, ub[(size_t)(t - 1) * DINNER], acc);
    acc = fmaf(w3, ub[(size_t)t * DINNER], acc);
    acc = acc / (1.f + expf(-acc));
    uc[idx] = acc;
    __nv_bfloat16 h = __float2bfloat16(acc);
    uch[idx] = h;
    ucl[idx] = __float2bfloat16(acc - __bfloat162float(h));
}

// ============================================================
// Selective scan + skip + gate — block-staged, TCHUNK=64
// ============================================================
#define TCHUNK 64
#define SC_OFF_UC 4096
#define SC_OFF_Z  8192
#define SC_OFF_BC 12288
#define SC_STAGE 20480
#define SC_NCH (LSEQ / TCHUNK)

__global__ __launch_bounds__(256) void scan_gate_k(
    const float* __restrict__ dt, const float* __restrict__ uc,
    const float* __restrict__ dblp, const float* __restrict__ z,
    const float* __restrict__ A_log, const float* __restrict__ D_skip,
    __half* __restrict__ yg16)
{
    __shared__ __align__(16) char sm[2 * SC_STAGE + TCHUNK * 16 * 2];
    const uint32_t sb = smem_to_u32(sm);
    __half* sy = (__half*)(sm + 2 * SC_STAGE);

    const int tid = threadIdx.x;
    const int w = tid >> 5;
    const int lane = tid & 31;
    const int el = 2 * w + (lane >> 4);
    const int n = lane & 15;
    const int e0 = blockIdx.x * 16;
    const int b = blockIdx.y;
    const int e = e0 + el;
    const size_t bt0 = (size_t)b * LSEQ;

    const float Aen = -expf(A_log[e * DSTATE + n]);
    const float dsk = D_skip[e];
    float h = 0.f;

    auto load_stage = [&](int st, int t0) {
        const uint32_t s = sb + st * SC_STAGE;
#pragma unroll
        for (int i2 = 0; i2 < 5; i2++) {
            int i = tid + i2 * 256;
            if (i < 256) {
                int t = i >> 2, p = i & 3;
                cp_async16(s + t * 64 + p * 16, dt + (bt0 + t0 + t) * DINNER + e0 + p * 4);
            } else if (i < 512) {
                int j = i - 256; int t = j >> 2, p = j & 3;
                cp_async16(s + SC_OFF_UC + t * 64 + p * 16, uc + (bt0 + t0 + t) * DINNER + e0 + p * 4);
            } else if (i < 768) {
                int j = i - 512; int t = j >> 2, p = j & 3;
                cp_async16(s + SC_OFF_Z + t * 64 + p * 16, z + (bt0 + t0 + t) * DINNER + e0 + p * 4);
            } else if (i < 1280) {
                int j = i - 768; int t = j >> 3, p = j & 7;
                cp_async16(s + SC_OFF_BC + t * 128 + p * 16, dblp + (bt0 + t0 + t) * DBLP_N + DTRANK + p * 4);
            }
        }
    };

    load_stage(0, 0); CP_COMMIT();

    for (int c = 0; c < SC_NCH; c++) {
        if (c + 1 < SC_NCH) { load_stage((c + 1) & 1, (c + 1) * TCHUNK); CP_COMMIT(); CP_WAIT(1); }
        else CP_WAIT(0);
        __syncthreads();

        const char* s = sm + (c & 1) * SC_STAGE;
        const float* sdt = (const float*)s;
        const float* suc = (const float*)(s + SC_OFF_UC);
        const float* sz  = (const float*)(s + SC_OFF_Z);
        const float* sbc = (const float*)(s + SC_OFF_BC);

#pragma unroll 4
        for (int tt = 0; tt < TCHUNK; tt++) {
            float dtv = sdt[tt * 16 + el];
            float ucv = suc[tt * 16 + el];
            float Bc = sbc[tt * 32 + n];
            float Cc = sbc[tt * 32 + 16 + n];
            float a = expf(dtv * Aen);
            h = fmaf(a, h, dtv * ucv * Bc);
            float p = h * Cc;
            p += __shfl_xor_sync(0xffffffffu, p, 1);
            p += __shfl_xor_sync(0xffffffffu, p, 2);
            p += __shfl_xor_sync(0xffffffffu, p, 4);
            p += __shfl_xor_sync(0xffffffffu, p, 8);
            if (n == 0) {
                float zv = sz[tt * 16 + el];
                float y = fmaf(ucv, dsk, p);
                y = y * (zv / (1.f + expf(-zv)));
                sy[tt * 16 + el] = __float2half(y);
            }
        }
        __syncthreads();
        // paired 32-bit stores (2 halves/iteration)
        for (int i = tid; i < TCHUNK * 8; i += 256) {
            int t = i >> 3, e2 = (i & 7) * 2;
            *(uint32_t*)&yg16[(bt0 + c * TCHUNK + t) * DINNER + e0 + e2] =
                *(const uint32_t*)&sy[t * 16 + e2];
        }
        __syncthreads();
    }
}

// ============================================================
// Launcher
// ============================================================
extern "C" void kernel_launch(void* const* d_in, const int* in_sizes, int n_in,
                              void* d_out, int out_size)
{
    const float* x      = (const float*)d_in[0];
    const float* ln_g   = (const float*)d_in[1];
    const float* ln_b   = (const float*)d_in[2];
    const float* W_in   = (const float*)d_in[3];
    const float* conv_w = (const float*)d_in[4];
    const float* conv_b = (const float*)d_in[5];
    const float* W_x    = (const float*)d_in[6];
    const float* W_dt   = (const float*)d_in[7];
    const float* b_dt   = (const float*)d_in[8];
    const float* A_log  = (const float*)d_in[9];
    const float* D_skip = (const float*)d_in[10];
    const float* W_out  = (const float*)d_in[11];
    float* out = (float*)d_out;

    __nv_bfloat16 *xh, *xl, *WinTh, *WinTl, *uch, *ucl, *WxTh, *WxTl;
    __nv_bfloat16 *dtAh, *dtAl, *WdtTh, *WdtTl;
    __half *x16, *WzT16, *yg16, *WoutT16;
    float *u, *z, *uc, *dblpp, *dblp, *dt;
    cudaGetSymbolAddress((void**)&xh, g_xh);       cudaGetSymbolAddress((void**)&xl, g_xl);
    cudaGetSymbolAddress((void**)&x16, g_x16);
    cudaGetSymbolAddress((void**)&WinTh, g_WinTh); cudaGetSymbolAddress((void**)&WinTl, g_WinTl);
    cudaGetSymbolAddress((void**)&WzT16, g_WzT16);
    cudaGetSymbolAddress((void**)&u, g_u);         cudaGetSymbolAddress((void**)&z, g_z);
    cudaGetSymbolAddress((void**)&uc, g_uc);
    cudaGetSymbolAddress((void**)&uch, g_uch);     cudaGetSymbolAddress((void**)&ucl, g_ucl);
    cudaGetSymbolAddress((void**)&WxTh, g_WxTh);   cudaGetSymbolAddress((void**)&WxTl, g_WxTl);
    cudaGetSymbolAddress((void**)&dblpp, g_dblpp); cudaGetSymbolAddress((void**)&dblp, g_dblp);
    cudaGetSymbolAddress((void**)&dtAh, g_dtAh);   cudaGetSymbolAddress((void**)&dtAl, g_dtAl);
    cudaGetSymbolAddress((void**)&WdtTh, g_WdtTh); cudaGetSymbolAddress((void**)&WdtTl, g_WdtTl);
    cudaGetSymbolAddress((void**)&dt, g_dt);
    cudaGetSymbolAddress((void**)&yg16, g_yg16);   cudaGetSymbolAddress((void**)&WoutT16, g_WoutT16);

    cudaFuncSetAttribute(gemm3_k<0, 0>, cudaFuncAttributeMaxDynamicSharedMemorySize, G3_SMEM);
    cudaFuncSetAttribute(gemm3_k<0, 1>, cudaFuncAttributeMaxDynamicSharedMemorySize, G3_SMEM);
    cudaFuncSetAttribute(gemm3_k<1, 0>, cudaFuncAttributeMaxDynamicSharedMemorySize, G3_SMEM);
    cudaFuncSetAttribute(gemmh_k, cudaFuncAttributeMaxDynamicSharedMemorySize, GH_SMEM);

    static cudaStream_t s1 = nullptr, s2 = nullptr, s3 = nullptr;
    static cudaEvent_t evRoot = nullptr, evLN = nullptr, evTu = nullptr,
                       evPrep = nullptr, evZ = nullptr;
    if (!s1) {
        cudaStreamCreateWithFlags(&s1, cudaStreamNonBlocking);
        cudaStreamCreateWithFlags(&s2, cudaStreamNonBlocking);
        cudaStreamCreateWithFlags(&s3, cudaStreamNonBlocking);
        cudaEventCreateWithFlags(&evRoot, cudaEventDisableTiming);
        cudaEventCreateWithFlags(&evLN, cudaEventDisableTiming);
        cudaEventCreateWithFlags(&evTu, cudaEventDisableTiming);
        cudaEventCreateWithFlags(&evPrep, cudaEventDisableTiming);
        cudaEventCreateWithFlags(&evZ, cudaEventDisableTiming);
    }

    cudaEventRecord(evRoot, 0);
    cudaStreamWaitEvent(s1, evRoot, 0);
    cudaStreamWaitEvent(s2, evRoot, 0);
    cudaStreamWaitEvent(s3, evRoot, 0);

    // [main #1] LayerNorm
    layernorm_k<<<NROWS, 256, 0, 0>>>(x, ln_g, ln_b, xh, xl, x16);
    cudaEventRecord(evLN, 0);

    // [s1 #2] W_in u-half transpose
    transpose_split_k<<<dim3(64, 32), dim3(32, 8), 0, s1>>>(W_in, WinTh, WinTl, DIMM, 2 * DINNER, 0, DINNER, DINNER);
    cudaEventRecord(evTu, s1);

    // [s2 #3] W_in z-half transpose
    transpose_h_k<<<dim3(64, 32), dim3(32, 8), 0, s2>>>(W_in, WzT16, DIMM, 2 * DINNER, DINNER, DINNER, DINNER);

    // [s2 #4] z = xn @ W_in[:, 2048:]  (fp16)  <-- ncu target
    cudaStreamWaitEvent(s2, evLN, 0);
    gemmh_k<<<dim3(DINNER / 128, NROWS / 128), 256, GH_SMEM, s2>>>(
        x16, WzT16, z, DIMM, DIMM, DINNER);
    cudaEventRecord(evZ, s2);

    // [main #5] u = xn @ W_in[:, :2048]  (bf16x3)
    cudaStreamWaitEvent(0, evTu, 0);
    gemm3_k<0, 0><<<dim3(DINNER / 128, NROWS / 128), 256, G3_SMEM, 0>>>(
        xh, xl, WinTh, WinTl, u, nullptr, DIMM, DIMM, DINNER);

    // [s3] remaining weight prep
    transpose_split_k<<<dim3(4, 64), dim3(32, 8), 0, s3>>>(W_x, WxTh, WxTl, DINNER, 96, 0, 96, DBLP_N);
    transpose_split_k<<<dim3(64, 2), dim3(32, 8), 0, s3>>>(W_dt, WdtTh, WdtTl, DTRANK, DINNER, 0, DINNER, DINNER);
    transpose_h_k<<<dim3(32, 64), dim3(32, 8), 0, s3>>>(W_out, WoutT16, DINNER, DIMM, 0, DIMM, DIMM);
    cudaEventRecord(evPrep, s3);

    // [main] conv + SiLU
    conv_silu_k<<<(BATCH * LSEQ * DINNER + 255) / 256, 256, 0, 0>>>(u, conv_w, conv_b, uc, uch, ucl);

    // [main] dblp partials = uc @ W_x (deterministic split-K x16)
    cudaStreamWaitEvent(0, evPrep, 0);
    gemm3_k<0, 1><<<dim3(1, NROWS / 128, KSPLIT), 256, G3_SMEM, 0>>>(
        uch, ucl, WxTh, WxTl, dblpp, nullptr, DINNER, DINNER / KSPLIT, DBLP_N);

    // [main] deterministic reduce + dtA split
    reduce_dta_k<<<(NROWS * DBLP_N / 4 + 255) / 256, 256, 0, 0>>>(dblpp, dblp, dtAh, dtAl);

    // [main] dt = softplus(dtA @ W_dt + b_dt)
    gemm3_k<1, 0><<<dim3(DINNER / 128, NROWS / 128), 256, G3_SMEM, 0>>>(
        dtAh, dtAl, WdtTh, WdtTl, dt, b_dt, DTRANK, DTRANK, DINNER);

    // [main] scan (needs z)
    cudaStreamWaitEvent(0, evZ, 0);
    scan_gate_k<<<dim3(DINNER / 16, BATCH), 256, 0, 0>>>(
        dt, uc, dblp, z, A_log, D_skip, yg16);

    // [main] out = yg @ W_out  (fp16)
    gemmh_k<<<dim3(DIMM / 128, NROWS / 128), 256, GH_SMEM, 0>>>(
        yg16, WoutT16, out, DINNER, DINNER, DIMM);
}

// round 15
// speedup vs baseline: 1.3370x; 1.0050x over previous
#include <cuda_runtime.h>
#include <cuda_bf16.h>
#include <cuda_fp16.h>
#include <cstdint>
#include <math.h>

#define BATCH 2
#define LSEQ 1024
#define DIMM 1024
#define DSTATE 16
#define DINNER 2048
#define DTRANK 64
#define NROWS (BATCH * LSEQ)   // 2048
#define DBLP_N 128             // padded 96 -> 128
#define KSPLIT 16

// ---------------- scratch ----------------
__device__ __align__(128) __nv_bfloat16 g_xh[NROWS * DIMM];
__device__ __align__(128) __nv_bfloat16 g_xl[NROWS * DIMM];
__device__ __align__(128) __half        g_x16[NROWS * DIMM];
__device__ __align__(128) __nv_bfloat16 g_WinTh[DINNER * DIMM];
__device__ __align__(128) __nv_bfloat16 g_WinTl[DINNER * DIMM];
__device__ __align__(128) __half        g_WzT16[DINNER * DIMM];
__device__ __align__(128) float         g_u[NROWS * DINNER];
__device__ __align__(128) float         g_z[NROWS * DINNER];
__device__ __align__(128) float         g_uc[NROWS * DINNER];
__device__ __align__(128) __nv_bfloat16 g_uch[NROWS * DINNER];
__device__ __align__(128) __nv_bfloat16 g_ucl[NROWS * DINNER];
__device__ __align__(128) __nv_bfloat16 g_WxTh[DBLP_N * DINNER];
__device__ __align__(128) __nv_bfloat16 g_WxTl[DBLP_N * DINNER];
__device__ __align__(128) float         g_dblpp[KSPLIT * NROWS * DBLP_N];
__device__ __align__(128) float         g_dblp[NROWS * DBLP_N];
__device__ __align__(128) __nv_bfloat16 g_dtAh[NROWS * DTRANK];
__device__ __align__(128) __nv_bfloat16 g_dtAl[NROWS * DTRANK];
__device__ __align__(128) __nv_bfloat16 g_WdtTh[DINNER * DTRANK];
__device__ __align__(128) __nv_bfloat16 g_WdtTl[DINNER * DTRANK];
__device__ __align__(128) float         g_dt[NROWS * DINNER];
__device__ __align__(128) __half        g_yg16[NROWS * DINNER];
__device__ __align__(128) __half        g_WoutT16[DIMM * DINNER];

// ---------------- helpers ----------------
__device__ __forceinline__ uint32_t smem_to_u32(const void* p) {
    uint32_t a;
    asm("{ .reg .u64 t; cvta.to.shared.u64 t, %1; cvt.u32.u64 %0, t; }" : "=r"(a) : "l"(p));
    return a;
}
__device__ __forceinline__ void cp_async16(uint32_t dst, const void* src) {
    asm volatile("cp.async.cg.shared.global [%0], [%1], 16;" :: "r"(dst), "l"(src) : "memory");
}
#define CP_COMMIT() asm volatile("cp.async.commit_group;" ::: "memory")
#define CP_WAIT(n)  asm volatile("cp.async.wait_group %0;" :: "n"(n) : "memory")

__device__ __forceinline__ void ldm_x4(uint32_t addr, uint32_t& r0, uint32_t& r1,
                                       uint32_t& r2, uint32_t& r3) {
    asm volatile("ldmatrix.sync.aligned.m8n8.x4.shared.b16 {%0,%1,%2,%3}, [%4];"
                 : "=r"(r0), "=r"(r1), "=r"(r2), "=r"(r3) : "r"(addr));
}
__device__ __forceinline__ void mma_bf16(float* c, const uint32_t* a, const uint32_t* b) {
    asm volatile(
        "mma.sync.aligned.m16n8k16.row.col.f32.bf16.bf16.f32 "
        "{%0,%1,%2,%3}, {%4,%5,%6,%7}, {%8,%9}, {%0,%1,%2,%3};"
        : "+f"(c[0]), "+f"(c[1]), "+f"(c[2]), "+f"(c[3])
        : "r"(a[0]), "r"(a[1]), "r"(a[2]), "r"(a[3]), "r"(b[0]), "r"(b[1]));
}
__device__ __forceinline__ void mma_fp16(float* c, const uint32_t* a, const uint32_t* b) {
    asm volatile(
        "mma.sync.aligned.m16n8k16.row.col.f32.f16.f16.f32 "
        "{%0,%1,%2,%3}, {%4,%5,%6,%7}, {%8,%9}, {%0,%1,%2,%3};"
        : "+f"(c[0]), "+f"(c[1]), "+f"(c[2]), "+f"(c[3])
        : "r"(a[0]), "r"(a[1]), "r"(a[2]), "r"(a[3]), "r"(b[0]), "r"(b[1]));
}

#define PITCH 80
#define TILE_B (128 * PITCH)
#define G3_STAGE (4 * TILE_B)
#define G3_SMEM (4 * G3_STAGE + 128)
#define GH_STAGE (2 * TILE_B)
#define GH_SMEM (4 * GH_STAGE + 128)

// ============================================================
// bf16x3 HMMA GEMM — 4-stage. SPLIT: deterministic split-K partials.
// ============================================================
template <int EPI, int SPLIT>
__global__ __launch_bounds__(256, 1) void gemm3_k(
    const __nv_bfloat16* __restrict__ Ah, const __nv_bfloat16* __restrict__ Al,
    const __nv_bfloat16* __restrict__ Bh, const __nv_bfloat16* __restrict__ Bl,
    float* __restrict__ C, const float* __restrict__ bias,
    int ld, int kLen, int ldc)
{
    extern __shared__ char smraw[];
    const uint32_t s0 = (smem_to_u32(smraw) + 127) & ~127u;

    const int tid = threadIdx.x;
    const int wid = tid >> 5;
    const int lane = tid & 31;
    const int wr = wid >> 2;
    const int wc = wid & 3;
    const int row0 = blockIdx.y * 128;
    const int col0 = blockIdx.x * 128;
    const int kBase = blockIdx.z * kLen;

    float acc[4][4][4];
#pragma unroll
    for (int i = 0; i < 4; i++)
#pragma unroll
        for (int j = 0; j < 4; j++)
#pragma unroll
            for (int q = 0; q < 4; q++) acc[i][j][q] = 0.f;

    const int NC = kLen >> 5;

    auto load_stage = [&](int stage, int kOff) {
        const uint32_t sbuf = s0 + stage * G3_STAGE;
#pragma unroll
        for (int t = 0; t < 4; t++) {
            const __nv_bfloat16* src = (t == 0) ? Ah : (t == 1) ? Al : (t == 2) ? Bh : Bl;
            const int rb = (t < 2) ? row0 : col0;
            const __nv_bfloat16* base = src + (size_t)rb * ld + kBase + kOff;
#pragma unroll
            for (int i2 = 0; i2 < 2; i2++) {
                int i = tid + i2 * 256;
                int r = i >> 2, c4 = i & 3;
                cp_async16(sbuf + t * TILE_B + r * PITCH + c4 * 16,
                           base + (size_t)r * ld + c4 * 8);
            }
        }
    };

    load_stage(0, 0); CP_COMMIT();
    load_stage(1, 32); CP_COMMIT();

    const int a_r = ((lane >> 3) & 1) * 8 + (lane & 7);
    const int a_c = (lane >> 4) * 8;
    const int b_r = ((lane >> 4) & 1) * 8 + (lane & 7);
    const int b_c = ((lane >> 3) & 1) * 8;

    for (int c = 0; c < NC; c++) {
        if (c + 2 < NC) load_stage((c + 2) & 3, (c + 2) << 5);
        CP_COMMIT();
        CP_WAIT(2);
        __syncthreads();

        const uint32_t stg = s0 + (c & 3) * G3_STAGE;
#pragma unroll
        for (int s = 0; s < 2; s++) {
            const int k0 = s * 16;
            uint32_t fAh[4][4], fAl[4][4], fBh[4][2], fBl[4][2];
#pragma unroll
            for (int i = 0; i < 4; i++) {
                uint32_t ar = stg + (wr * 64 + i * 16 + a_r) * PITCH + (k0 + a_c) * 2;
                ldm_x4(ar, fAh[i][0], fAh[i][1], fAh[i][2], fAh[i][3]);
                ldm_x4(ar + TILE_B, fAl[i][0], fAl[i][1], fAl[i][2], fAl[i][3]);
            }
#pragma unroll
            for (int j2 = 0; j2 < 2; j2++) {
                uint32_t br = stg + 2 * TILE_B + (wc * 32 + j2 * 16 + b_r) * PITCH + (k0 + b_c) * 2;
                uint32_t r0, r1, r2, r3;
                ldm_x4(br, r0, r1, r2, r3);
                fBh[j2 * 2][0] = r0; fBh[j2 * 2][1] = r1;
                fBh[j2 * 2 + 1][0] = r2; fBh[j2 * 2 + 1][1] = r3;
                ldm_x4(br + TILE_B, r0, r1, r2, r3);
                fBl[j2 * 2][0] = r0; fBl[j2 * 2][1] = r1;
                fBl[j2 * 2 + 1][0] = r2; fBl[j2 * 2 + 1][1] = r3;
            }
#pragma unroll
            for (int i = 0; i < 4; i++)
#pragma unroll
                for (int j = 0; j < 4; j++) mma_bf16(acc[i][j], fAh[i], fBh[j]);
#pragma unroll
            for (int i = 0; i < 4; i++)
#pragma unroll
                for (int j = 0; j < 4; j++) mma_bf16(acc[i][j], fAh[i], fBl[j]);
#pragma unroll
            for (int i = 0; i < 4; i++)
#pragma unroll
                for (int j = 0; j < 4; j++) mma_bf16(acc[i][j], fAl[i], fBh[j]);
        }
        __syncthreads();
    }

    float* Cz = SPLIT ? (C + (size_t)blockIdx.z * NROWS * ldc) : C;
    const int er = lane >> 2;
    const int ec = (lane & 3) * 2;
#pragma unroll
    for (int i = 0; i < 4; i++) {
#pragma unroll
        for (int j = 0; j < 4; j++) {
            int grow = row0 + wr * 64 + i * 16 + er;
            int gcol = col0 + wc * 32 + j * 8 + ec;
            float v0 = acc[i][j][0], v1 = acc[i][j][1];
            float v2 = acc[i][j][2], v3 = acc[i][j][3];
            if (EPI == 1) {
                float b0 = bias[gcol], b1 = bias[gcol + 1];
                v0 += b0; v1 += b1; v2 += b0; v3 += b1;
                v0 = fmaxf(v0, 0.f) + log1pf(__expf(-fabsf(v0)));
                v1 = fmaxf(v1, 0.f) + log1pf(__expf(-fabsf(v1)));
                v2 = fmaxf(v2, 0.f) + log1pf(__expf(-fabsf(v2)));
                v3 = fmaxf(v3, 0.f) + log1pf(__expf(-fabsf(v3)));
            }
            *(float2*)&Cz[(size_t)grow * ldc + gcol] = make_float2(v0, v1);
            *(float2*)&Cz[(size_t)(grow + 8) * ldc + gcol] = make_float2(v2, v3);
        }
    }
}

// ============================================================
// Deterministic split-K reduce + dtA split (merged)
// ============================================================
__global__ __launch_bounds__(256) void reduce_dta_k(
    const float* __restrict__ part, float* __restrict__ dblp,
    __nv_bfloat16* __restrict__ dtAh, __nv_bfloat16* __restrict__ dtAl)
{
    int idx = blockIdx.x * blockDim.x + threadIdx.x;
    if (idx >= NROWS * DBLP_N / 4) return;
    float4 s = ((const float4*)part)[idx];
#pragma unroll
    for (int k = 1; k < KSPLIT; k++) {
        float4 v = ((const float4*)(part + (size_t)k * NROWS * DBLP_N))[idx];
        s.x += v.x; s.y += v.y; s.z += v.z; s.w += v.w;
    }
    ((float4*)dblp)[idx] = s;

    int c4 = idx & 31;
    if (c4 < 16) {
        int r = idx >> 5;
        int col = c4 * 4;
        float v[4] = {s.x, s.y, s.z, s.w};
        __nv_bfloat16 h[4], l[4];
#pragma unroll
        for (int q = 0; q < 4; q++) {
            h[q] = __float2bfloat16(v[q]);
            l[q] = __float2bfloat16(v[q] - __bfloat162float(h[q]));
        }
        *(uint2*)&dtAh[(size_t)r * DTRANK + col] = *(uint2*)h;
        *(uint2*)&dtAl[(size_t)r * DTRANK + col] = *(uint2*)l;
    }
}

// ============================================================
// fp16 1-term HMMA GEMM — R10/R14 verified config (2 CTAs/SM)
// ============================================================
__global__ __launch_bounds__(256, 2) void gemmh_k(
    const __half* __restrict__ A, const __half* __restrict__ B,
    float* __restrict__ C, int ld, int kLen, int ldc)
{
    extern __shared__ char smraw[];
    const uint32_t s0 = (smem_to_u32(smraw) + 127) & ~127u;

    const int tid = threadIdx.x;
    const int wid = tid >> 5;
    const int lane = tid & 31;
    const int wr = wid >> 2;
    const int wc = wid & 3;
    const int row0 = blockIdx.y * 128;
    const int col0 = blockIdx.x * 128;

    float acc[4][4][4];
#pragma unroll
    for (int i = 0; i < 4; i++)
#pragma unroll
        for (int j = 0; j < 4; j++)
#pragma unroll
            for (int q = 0; q < 4; q++) acc[i][j][q] = 0.f;

    const int NC = kLen >> 5;

    auto load_stage = [&](int stage, int kOff) {
        const uint32_t sbuf = s0 + stage * GH_STAGE;
#pragma unroll
        for (int t = 0; t < 2; t++) {
            const __half* src = (t == 0) ? A : B;
            const int rb = (t == 0) ? row0 : col0;
            const __half* base = src + (size_t)rb * ld + kOff;
#pragma unroll
            for (int i2 = 0; i2 < 2; i2++) {
                int ii = tid + i2 * 256;
                int r = ii >> 2, c4 = ii & 3;
                cp_async16(sbuf + t * TILE_B + r * PITCH + c4 * 16,
                           base + (size_t)r * ld + c4 * 8);
            }
        }
    };

    load_stage(0, 0); CP_COMMIT();
    load_stage(1, 32); CP_COMMIT();

    const int a_r = ((lane >> 3) & 1) * 8 + (lane & 7);
    const int a_c = (lane >> 4) * 8;
    const int b_r = ((lane >> 4) & 1) * 8 + (lane & 7);
    const int b_c = ((lane >> 3) & 1) * 8;

    for (int c = 0; c < NC; c++) {
        if (c + 2 < NC) load_stage((c + 2) & 3, (c + 2) << 5);
        CP_COMMIT();
        CP_WAIT(2);
        __syncthreads();

        const uint32_t stg = s0 + (c & 3) * GH_STAGE;
#pragma unroll
        for (int s = 0; s < 2; s++) {
            const int k0 = s * 16;
            uint32_t fA[4][4], fB[4][2];
#pragma unroll
            for (int i = 0; i < 4; i++) {
                uint32_t ar = stg + (wr * 64 + i * 16 + a_r) * PITCH + (k0 + a_c) * 2;
                ldm_x4(ar, fA[i][0], fA[i][1], fA[i][2], fA[i][3]);
            }
#pragma unroll
            for (int j2 = 0; j2 < 2; j2++) {
                uint32_t br = stg + TILE_B + (wc * 32 + j2 * 16 + b_r) * PITCH + (k0 + b_c) * 2;
                uint32_t r0, r1, r2, r3;
                ldm_x4(br, r0, r1, r2, r3);
                fB[j2 * 2][0] = r0; fB[j2 * 2][1] = r1;
                fB[j2 * 2 + 1][0] = r2; fB[j2 * 2 + 1][1] = r3;
            }
#pragma unroll
            for (int i = 0; i < 4; i++)
#pragma unroll
                for (int j = 0; j < 4; j++) mma_fp16(acc[i][j], fA[i], fB[j]);
        }
        __syncthreads();
    }

    const int er = lane >> 2;
    const int ec = (lane & 3) * 2;
#pragma unroll
    for (int i = 0; i < 4; i++)
#pragma unroll
        for (int j = 0; j < 4; j++) {
            int grow = row0 + wr * 64 + i * 16 + er;
            int gcol = col0 + wc * 32 + j * 8 + ec;
            *(float2*)&C[(size_t)grow * ldc + gcol] = make_float2(acc[i][j][0], acc[i][j][1]);
            *(float2*)&C[(size_t)(grow + 8) * ldc + gcol] = make_float2(acc[i][j][2], acc[i][j][3]);
        }
}

// ============================================================
// LayerNorm -> bf16 hi/lo + fp16
// ============================================================
__global__ __launch_bounds__(256) void layernorm_k(
    const float* __restrict__ x, const float* __restrict__ g,
    const float* __restrict__ b, __nv_bfloat16* __restrict__ xh,
    __nv_bfloat16* __restrict__ xl, __half* __restrict__ x16)
{
    const int row = blockIdx.x;
    const float* xr = x + (size_t)row * DIMM;
    float v[4];
    float s = 0.f;
#pragma unroll
    for (int i = 0; i < 4; i++) { v[i] = xr[threadIdx.x + i * 256]; s += v[i]; }
    __shared__ float red[32];
    for (int o = 16; o > 0; o >>= 1) s += __shfl_xor_sync(0xffffffffu, s, o);
    int lane = threadIdx.x & 31, wid = threadIdx.x >> 5;
    if (lane == 0) red[wid] = s;
    __syncthreads();
    if (wid == 0) {
        float t = (lane < 8) ? red[lane] : 0.f;
        for (int o = 4; o > 0; o >>= 1) t += __shfl_xor_sync(0xffffffffu, t, o);
        if (lane == 0) red[0] = t;
    }
    __syncthreads();
    const float mu = red[0] * (1.f / DIMM);
    float s2 = 0.f;
#pragma unroll
    for (int i = 0; i < 4; i++) { float d = v[i] - mu; s2 += d * d; }
    for (int o = 16; o > 0; o >>= 1) s2 += __shfl_xor_sync(0xffffffffu, s2, o);
    if (lane == 0) red[wid] = s2;
    __syncthreads();
    if (wid == 0) {
        float t = (lane < 8) ? red[lane] : 0.f;
        for (int o = 4; o > 0; o >>= 1) t += __shfl_xor_sync(0xffffffffu, t, o);
        if (lane == 0) red[0] = t;
    }
    __syncthreads();
    const float rstd = rsqrtf(red[0] * (1.f / DIMM) + 1e-5f);
#pragma unroll
    for (int i = 0; i < 4; i++) {
        int c = threadIdx.x + i * 256;
        float o = (v[i] - mu) * rstd * g[c] + b[c];
        __nv_bfloat16 h = __float2bfloat16(o);
        xh[(size_t)row * DIMM + c] = h;
        xl[(size_t)row * DIMM + c] = __float2bfloat16(o - __bfloat162float(h));
        x16[(size_t)row * DIMM + c] = __float2half(o);
    }
}

// ============================================================
// Merged W_in transpose: one pass over W_in [1024, 4096];
// cols < 2048 -> WinTh/WinTl, cols >= 2048 -> WzT16.
// ============================================================
__global__ __launch_bounds__(256) void transpose_win_k(
    const float* __restrict__ W_in, __nv_bfloat16* __restrict__ oh,
    __nv_bfloat16* __restrict__ ol, __half* __restrict__ o16)
{
    __shared__ float t[32][33];
    int tx = threadIdx.x, ty = threadIdx.y;
    int c0 = blockIdx.x * 32, r0 = blockIdx.y * 32;
#pragma unroll
    for (int j = 0; j < 32; j += 8)
        t[ty + j][tx] = W_in[(size_t)(r0 + ty + j) * (2 * DINNER) + c0 + tx];
    __syncthreads();
#pragma unroll
    for (int j = 0; j < 32; j += 8) {
        int ocol_w = c0 + ty + j;   // 0..4095 (W_in column = output row)
        int orow = r0 + tx;         // 0..1023
        float v = t[tx][ty + j];
        if (ocol_w < DINNER) {
            __nv_bfloat16 h = __float2bfloat16(v);
            oh[(size_t)ocol_w * DIMM + orow] = h;
            ol[(size_t)ocol_w * DIMM + orow] = __float2bfloat16(v - __bfloat162float(h));
        } else {
            o16[(size_t)(ocol_w - DINNER) * DIMM + orow] = __float2half(v);
        }
    }
}

// generic transposes (weight prep for W_x / W_dt / W_out)
__global__ __launch_bounds__(256) void transpose_split_k(
    const float* __restrict__ src, __nv_bfloat16* __restrict__ oh,
    __nv_bfloat16* __restrict__ ol, int R, int Cs, int co, int Cr, int Cout)
{
    __shared__ float t[32][33];
    int tx = threadIdx.x, ty = threadIdx.y;
    int c0 = blockIdx.x * 32, r0 = blockIdx.y * 32;
#pragma unroll
    for (int j = 0; j < 32; j += 8) {
        int r = r0 + ty + j, c = c0 + tx;
        t[ty + j][tx] = (r < R && c < Cr) ? src[(size_t)r * Cs + co + c] : 0.f;
    }
    __syncthreads();
#pragma unroll
    for (int j = 0; j < 32; j += 8) {
        int orow = c0 + ty + j, ocol = r0 + tx;
        if (orow < Cout && ocol < R) {
            float v = t[tx][ty + j];
            __nv_bfloat16 h = __float2bfloat16(v);
            oh[(size_t)orow * R + ocol] = h;
            ol[(size_t)orow * R + ocol] = __float2bfloat16(v - __bfloat162float(h));
        }
    }
}

__global__ __launch_bounds__(256) void transpose_h_k(
    const float* __restrict__ src, __half* __restrict__ o16,
    int R, int Cs, int co, int Cr, int Cout)
{
    __shared__ float t[32][33];
    int tx = threadIdx.x, ty = threadIdx.y;
    int c0 = blockIdx.x * 32, r0 = blockIdx.y * 32;
#pragma unroll
    for (int j = 0; j < 32; j += 8) {
        int r = r0 + ty + j, c = c0 + tx;
        t[ty + j][tx] = (r < R && c < Cr) ? src[(size_t)r * Cs + co + c] : 0.f;
    }
    __syncthreads();
#pragma unroll
    for (int j = 0; j < 32; j += 8) {
        int orow = c0 + ty + j, ocol = r0 + tx;
        if (orow < Cout && ocol < R)
            o16[(size_t)orow * R + ocol] = __float2half(t[tx][ty + j]);
    }
}

// ============================================================
// conv + SiLU (fast exp)
// ============================================================
__global__ __launch_bounds__(256) void conv_silu_k(
    const float* __restrict__ u, const float* __restrict__ conv_w,
    const float* __restrict__ conv_b, float* __restrict__ uc,
    __nv_bfloat16* __restrict__ uch, __nv_bfloat16* __restrict__ ucl)
{
    int idx = blockIdx.x * blockDim.x + threadIdx.x;
    if (idx >= BATCH * LSEQ * DINNER) return;
    int e = idx & (DINNER - 1);
    int bt = idx >> 11;
    int t = bt & (LSEQ - 1);
    int b = bt >> 10;
    float acc = conv_b[e];
    float w0 = conv_w[e * 4 + 0], w1 = conv_w[e * 4 + 1];
    float w2 = conv_w[e * 4 + 2], w3 = conv_w[e * 4 + 3];
    const float* ub = u + (size_t)b * LSEQ * DINNER + e;
    if (t >= 3) acc = fmaf(w0, ub[(size_t)(t - 3) * DINNER], acc);
    if (t >= 2) acc = fmaf(w1, ub[(size_t)(t - 2) * DINNER], acc);
    if (t >= 1) acc = fmaf(w2, ub[(size_t)(t - 1) * DINNER], acc);
    acc = fmaf(w3, ub[(size_t)t * DINNER], acc);
    acc = acc / (1.f + __expf(-acc));
    uc[idx] = acc;
    __nv_bfloat16 h = __float2bfloat16(acc);
    uch[idx] = h;
    ucl[idx] = __float2bfloat16(acc - __bfloat162float(h));
}

// ============================================================
// Selective scan + skip + gate — block-staged, TCHUNK=64, fast exp
// ============================================================
#define TCHUNK 64
#define SC_OFF_UC 4096
#define SC_OFF_Z  8192
#define SC_OFF_BC 12288
#define SC_STAGE 20480
#define SC_NCH (LSEQ / TCHUNK)

__global__ __launch_bounds__(256) void scan_gate_k(
    const float* __restrict__ dt, const float* __restrict__ uc,
    const float* __restrict__ dblp, const float* __restrict__ z,
    const float* __restrict__ A_log, const float* __restrict__ D_skip,
    __half* __restrict__ yg16)
{
    __shared__ __align__(16) char sm[2 * SC_STAGE + TCHUNK * 16 * 2];
    const uint32_t sb = smem_to_u32(sm);
    __half* sy = (__half*)(sm + 2 * SC_STAGE);

    const int tid = threadIdx.x;
    const int w = tid >> 5;
    const int lane = tid & 31;
    const int el = 2 * w + (lane >> 4);
    const int n = lane & 15;
    const int e0 = blockIdx.x * 16;
    const int b = blockIdx.y;
    const int e = e0 + el;
    const size_t bt0 = (size_t)b * LSEQ;

    const float Aen = -expf(A_log[e * DSTATE + n]);   // one-time: accurate
    const float dsk = D_skip[e];
    float h = 0.f;

    auto load_stage = [&](int st, int t0) {
        const uint32_t s = sb + st * SC_STAGE;
#pragma unroll
        for (int i2 = 0; i2 < 5; i2++) {
            int i = tid + i2 * 256;
            if (i < 256) {
                int t = i >> 2, p = i & 3;
                cp_async16(s + t * 64 + p * 16, dt + (bt0 + t0 + t) * DINNER + e0 + p * 4);
            } else if (i < 512) {
                int j = i - 256; int t = j >> 2, p = j & 3;
                cp_async16(s + SC_OFF_UC + t * 64 + p * 16, uc + (bt0 + t0 + t) * DINNER + e0 + p * 4);
            } else if (i < 768) {
                int j = i - 512; int t = j >> 2, p = j & 3;
                cp_async16(s + SC_OFF_Z + t * 64 + p * 16, z + (bt0 + t0 + t) * DINNER + e0 + p * 4);
            } else if (i < 1280) {
                int j = i - 768; int t = j >> 3, p = j & 7;
                cp_async16(s + SC_OFF_BC + t * 128 + p * 16, dblp + (bt0 + t0 + t) * DBLP_N + DTRANK + p * 4);
            }
        }
    };

    load_stage(0, 0); CP_COMMIT();

    for (int c = 0; c < SC_NCH; c++) {
        if (c + 1 < SC_NCH) { load_stage((c + 1) & 1, (c + 1) * TCHUNK); CP_COMMIT(); CP_WAIT(1); }
        else CP_WAIT(0);
        __syncthreads();

        const char* s = sm + (c & 1) * SC_STAGE;
        const float* sdt = (const float*)s;
        const float* suc = (const float*)(s + SC_OFF_UC);
        const float* sz  = (const float*)(s + SC_OFF_Z);
        const float* sbc = (const float*)(s + SC_OFF_BC);

#pragma unroll 4
        for (int tt = 0; tt < TCHUNK; tt++) {
            float dtv = sdt[tt * 16 + el];
            float ucv = suc[tt * 16 + el];
            float Bc = sbc[tt * 32 + n];
            float Cc = sbc[tt * 32 + 16 + n];
            float a = __expf(dtv * Aen);
            h = fmaf(a, h, dtv * ucv * Bc);
            float p = h * Cc;
            p += __shfl_xor_sync(0xffffffffu, p, 1);
            p += __shfl_xor_sync(0xffffffffu, p, 2);
            p += __shfl_xor_sync(0xffffffffu, p, 4);
            p += __shfl_xor_sync(0xffffffffu, p, 8);
            if (n == 0) {
                float zv = sz[tt * 16 + el];
                float y = fmaf(ucv, dsk, p);
                y = y * (zv / (1.f + __expf(-zv)));
                sy[tt * 16 + el] = __float2half(y);
            }
        }
        __syncthreads();
        for (int i = tid; i < TCHUNK * 8; i += 256) {
            int t = i >> 3, e2 = (i & 7) * 2;
            *(uint32_t*)&yg16[(bt0 + c * TCHUNK + t) * DINNER + e0 + e2] =
                *(const uint32_t*)&sy[t * 16 + e2];
        }
        __syncthreads();
    }
}

// ============================================================
// Launcher — gemmh (z) at issue slot 4 for ncu
// ============================================================
extern "C" void kernel_launch(void* const* d_in, const int* in_sizes, int n_in,
                              void* d_out, int out_size)
{
    const float* x      = (const float*)d_in[0];
    const float* ln_g   = (const float*)d_in[1];
    const float* ln_b   = (const float*)d_in[2];
    const float* W_in   = (const float*)d_in[3];
    const float* conv_w = (const float*)d_in[4];
    const float* conv_b = (const float*)d_in[5];
    const float* W_x    = (const float*)d_in[6];
    const float* W_dt   = (const float*)d_in[7];
    const float* b_dt   = (const float*)d_in[8];
    const float* A_log  = (const float*)d_in[9];
    const float* D_skip = (const float*)d_in[10];
    const float* W_out  = (const float*)d_in[11];
    float* out = (float*)d_out;

    __nv_bfloat16 *xh, *xl, *WinTh, *WinTl, *uch, *ucl, *WxTh, *WxTl;
    __nv_bfloat16 *dtAh, *dtAl, *WdtTh, *WdtTl;
    __half *x16, *WzT16, *yg16, *WoutT16;
    float *u, *z, *uc, *dblpp, *dblp, *dt;
    cudaGetSymbolAddress((void**)&xh, g_xh);       cudaGetSymbolAddress((void**)&xl, g_xl);
    cudaGetSymbolAddress((void**)&x16, g_x16);
    cudaGetSymbolAddress((void**)&WinTh, g_WinTh); cudaGetSymbolAddress((void**)&WinTl, g_WinTl);
    cudaGetSymbolAddress((void**)&WzT16, g_WzT16);
    cudaGetSymbolAddress((void**)&u, g_u);         cudaGetSymbolAddress((void**)&z, g_z);
    cudaGetSymbolAddress((void**)&uc, g_uc);
    cudaGetSymbolAddress((void**)&uch, g_uch);     cudaGetSymbolAddress((void**)&ucl, g_ucl);
    cudaGetSymbolAddress((void**)&WxTh, g_WxTh);   cudaGetSymbolAddress((void**)&WxTl, g_WxTl);
    cudaGetSymbolAddress((void**)&dblpp, g_dblpp); cudaGetSymbolAddress((void**)&dblp, g_dblp);
    cudaGetSymbolAddress((void**)&dtAh, g_dtAh);   cudaGetSymbolAddress((void**)&dtAl, g_dtAl);
    cudaGetSymbolAddress((void**)&WdtTh, g_WdtTh); cudaGetSymbolAddress((void**)&WdtTl, g_WdtTl);
    cudaGetSymbolAddress((void**)&dt, g_dt);
    cudaGetSymbolAddress((void**)&yg16, g_yg16);   cudaGetSymbolAddress((void**)&WoutT16, g_WoutT16);

    cudaFuncSetAttribute(gemm3_k<0, 0>, cudaFuncAttributeMaxDynamicSharedMemorySize, G3_SMEM);
    cudaFuncSetAttribute(gemm3_k<0, 1>, cudaFuncAttributeMaxDynamicSharedMemorySize, G3_SMEM);
    cudaFuncSetAttribute(gemm3_k<1, 0>, cudaFuncAttributeMaxDynamicSharedMemorySize, G3_SMEM);
    cudaFuncSetAttribute(gemmh_k, cudaFuncAttributeMaxDynamicSharedMemorySize, GH_SMEM);

    static cudaStream_t s1 = nullptr, s2 = nullptr, s3 = nullptr;
    static cudaEvent_t evRoot = nullptr, evLN = nullptr, evTw = nullptr,
                       evPrep = nullptr, evZ = nullptr;
    if (!s1) {
        cudaStreamCreateWithFlags(&s1, cudaStreamNonBlocking);
        cudaStreamCreateWithFlags(&s2, cudaStreamNonBlocking);
        cudaStreamCreateWithFlags(&s3, cudaStreamNonBlocking);
        cudaEventCreateWithFlags(&evRoot, cudaEventDisableTiming);
        cudaEventCreateWithFlags(&evLN, cudaEventDisableTiming);
        cudaEventCreateWithFlags(&evTw, cudaEventDisableTiming);
        cudaEventCreateWithFlags(&evPrep, cudaEventDisableTiming);
        cudaEventCreateWithFlags(&evZ, cudaEventDisableTiming);
    }

    cudaEventRecord(evRoot, 0);
    cudaStreamWaitEvent(s1, evRoot, 0);
    cudaStreamWaitEvent(s2, evRoot, 0);
    cudaStreamWaitEvent(s3, evRoot, 0);

    // [main #1] LayerNorm
    layernorm_k<<<NROWS, 256, 0, 0>>>(x, ln_g, ln_b, xh, xl, x16);
    cudaEventRecord(evLN, 0);

    // [s1 #2] merged W_in transpose (u hi/lo + z fp16 in one pass)
    transpose_win_k<<<dim3(128, 32), dim3(32, 8), 0, s1>>>(W_in, WinTh, WinTl, WzT16);
    cudaEventRecord(evTw, s1);

    // [s3 #3] W_x transpose (independent filler so gemmh is slot 4)
    transpose_split_k<<<dim3(4, 64), dim3(32, 8), 0, s3>>>(W_x, WxTh, WxTl, DINNER, 96, 0, 96, DBLP_N);

    // [s2 #4] z = xn @ W_in[:, 2048:]  (fp16)  <-- ncu target
    cudaStreamWaitEvent(s2, evLN, 0);
    cudaStreamWaitEvent(s2, evTw, 0);
    gemmh_k<<<dim3(DINNER / 128, NROWS / 128), 256, GH_SMEM, s2>>>(
        x16, WzT16, z, DIMM, DIMM, DINNER);
    cudaEventRecord(evZ, s2);

    // [main #5] u = xn @ W_in[:, :2048]  (bf16x3)
    cudaStreamWaitEvent(0, evTw, 0);
    gemm3_k<0, 0><<<dim3(DINNER / 128, NROWS / 128), 256, G3_SMEM, 0>>>(
        xh, xl, WinTh, WinTl, u, nullptr, DIMM, DIMM, DINNER);

    // [s3] remaining weight prep
    transpose_split_k<<<dim3(64, 2), dim3(32, 8), 0, s3>>>(W_dt, WdtTh, WdtTl, DTRANK, DINNER, 0, DINNER, DINNER);
    transpose_h_k<<<dim3(32, 64), dim3(32, 8), 0, s3>>>(W_out, WoutT16, DINNER, DIMM, 0, DIMM, DIMM);
    cudaEventRecord(evPrep, s3);

    // [main] conv + SiLU
    conv_silu_k<<<(BATCH * LSEQ * DINNER + 255) / 256, 256, 0, 0>>>(u, conv_w, conv_b, uc, uch, ucl);

    // [main] dblp partials = uc @ W_x (deterministic split-K x16)
    cudaStreamWaitEvent(0, evPrep, 0);
    gemm3_k<0, 1><<<dim3(1, NROWS / 128, KSPLIT), 256, G3_SMEM, 0>>>(
        uch, ucl, WxTh, WxTl, dblpp, nullptr, DINNER, DINNER / KSPLIT, DBLP_N);

    // [main] deterministic reduce + dtA split
    reduce_dta_k<<<(NROWS * DBLP_N / 4 + 255) / 256, 256, 0, 0>>>(dblpp, dblp, dtAh, dtAl);

    // [main] dt = softplus(dtA @ W_dt + b_dt)
    gemm3_k<1, 0><<<dim3(DINNER / 128, NROWS / 128), 256, G3_SMEM, 0>>>(
        dtAh, dtAl, WdtTh, WdtTl, dt, b_dt, DTRANK, DTRANK, DINNER);

    // [main] scan (needs z)
    cudaStreamWaitEvent(0, evZ, 0);
    scan_gate_k<<<dim3(DINNER / 16, BATCH), 256, 0, 0>>>(
        dt, uc, dblp, z, A_log, D_skip, yg16);

    // [main] out = yg @ W_out  (fp16)
    gemmh_k<<<dim3(DIMM / 128, NROWS / 128), 256, GH_SMEM, 0>>>(
        yg16, WoutT16, out, DINNER, DINNER, DIMM);
}